// round 1
// baseline (speedup 1.0000x reference)
#include <cuda_runtime.h>
#include <math.h>

// Problem shape (fixed for this problem instance)
#define B_   2
#define S_   2048
#define D_   1024
#define H_   16
#define HD   64
#define MTOT (B_*S_)          // 4096
#define SCALE 0.125f          // 1/sqrt(64)

// ---------------- scratch (device globals; no allocations allowed) ----------
__device__ float g_q[(size_t)B_*H_*S_*HD];     // [B,H,S,hd]
__device__ float g_k[(size_t)B_*H_*S_*HD];
__device__ float g_v[(size_t)B_*H_*S_*HD];
__device__ float g_att[(size_t)B_*S_*D_];      // [B,S,D]

// ---------------- GEMM: C[m,n] = sum_k A[m,k] * W[n,k] ----------------------
// M=4096, N=1024, K=1024. BM=BN=128, BK=16, 256 threads, 8x8 microtile.
// ROPE: apply rotary embedding in the epilogue (pairs of adjacent columns).
// SCATTER: write to [B,H,S,hd] layout instead of [M,N].
#define BM 128
#define BN 128
#define BK 16

template<int ROPE, int SCATTER>
__global__ __launch_bounds__(256, 2)
void gemm_kernel(const float* __restrict__ A, const float* __restrict__ W,
                 float* __restrict__ C)
{
    __shared__ float As[BK][BM];
    __shared__ float Ws[BK][BN];

    const int tid = threadIdx.x;
    const int tx = tid & 15;          // 0..15  -> col group
    const int ty = tid >> 4;          // 0..15  -> row group
    const int m0 = blockIdx.y * BM;
    const int n0 = blockIdx.x * BN;

    float acc[8][8];
#pragma unroll
    for (int i = 0; i < 8; i++)
#pragma unroll
        for (int j = 0; j < 8; j++) acc[i][j] = 0.f;

    for (int k0 = 0; k0 < D_; k0 += BK) {
        // cooperative load: 128x16 floats each = 512 float4; 2 per thread
#pragma unroll
        for (int p = 0; p < 2; p++) {
            int idx = tid + p * 256;           // 0..511
            int row = idx >> 2;                // 0..127
            int c4  = (idx & 3) << 2;          // 0,4,8,12
            float4 a = *(const float4*)(A + (size_t)(m0 + row) * D_ + k0 + c4);
            As[c4+0][row] = a.x; As[c4+1][row] = a.y;
            As[c4+2][row] = a.z; As[c4+3][row] = a.w;
            float4 w = *(const float4*)(W + (size_t)(n0 + row) * D_ + k0 + c4);
            Ws[c4+0][row] = w.x; Ws[c4+1][row] = w.y;
            Ws[c4+2][row] = w.z; Ws[c4+3][row] = w.w;
        }
        __syncthreads();

#pragma unroll
        for (int k = 0; k < BK; k++) {
            float ra[8], rw[8];
#pragma unroll
            for (int i = 0; i < 8; i++) ra[i] = As[k][ty * 8 + i];
#pragma unroll
            for (int j = 0; j < 8; j++) rw[j] = Ws[k][tx * 8 + j];
#pragma unroll
            for (int i = 0; i < 8; i++)
#pragma unroll
                for (int j = 0; j < 8; j++)
                    acc[i][j] += ra[i] * rw[j];
        }
        __syncthreads();
    }

    // epilogue
#pragma unroll
    for (int i = 0; i < 8; i++) {
        const int m    = m0 + ty * 8 + i;
        const int spos = m & (S_ - 1);          // S_=2048 power of two
        const int b    = m >> 11;               // m / S_
#pragma unroll
        for (int j = 0; j < 8; j += 2) {
            const int n = n0 + tx * 8 + j;      // even
            float v1 = acc[i][j], v2 = acc[i][j+1];
            if (ROPE) {
                const int d = n & (HD - 1);     // even index within head
                float theta = powf(10000.0f, -(float)d * (1.0f / (float)HD));
                float ang = (float)spos * theta;
                float cc, ss;
                sincosf(ang, &ss, &cc);
                float y1 = v1 * cc - v2 * ss;
                float y2 = v1 * ss + v2 * cc;
                v1 = y1; v2 = y2;
            }
            if (SCATTER) {
                const int h = n >> 6;           // n / HD
                const int d = n & (HD - 1);
                float* p = C + (((size_t)(b * H_ + h) * S_) + spos) * HD + d;
                *(float2*)p = make_float2(v1, v2);
            } else {
                float* p = C + (size_t)m * D_ + n;
                *(float2*)p = make_float2(v1, v2);
            }
        }
    }
}

// ---------------- Flash attention (causal), fp32 ----------------------------
// Block = 64 threads, one Q row per thread. Q tile 64 rows; iterate K/V tiles
// of 64. K/V reads from smem are uniform-address broadcasts (conflict-free).
// Score staging uses a (j+t)&63 swizzle -> conflict-free, total smem = 48KB.
__global__ __launch_bounds__(64, 4)
void flash_kernel(const float* __restrict__ Q, const float* __restrict__ K,
                  const float* __restrict__ V, float* __restrict__ Oatt)
{
    __shared__ float Ks[64 * 64];
    __shared__ float Vs[64 * 64];
    __shared__ float Ss[64 * 64];   // swizzled per-thread score rows

    const int t  = threadIdx.x;     // q row within tile
    const int mt = blockIdx.x;      // q tile index
    const int bh = blockIdx.y;      // b*H + h

    // load own q row (pre-scaled)
    float q[64];
    const float* qp = Q + ((size_t)bh * S_ + (size_t)mt * 64 + t) * HD;
#pragma unroll
    for (int i = 0; i < 16; i++) {
        float4 f = *(const float4*)(qp + i * 4);
        q[i*4+0] = f.x * SCALE; q[i*4+1] = f.y * SCALE;
        q[i*4+2] = f.z * SCALE; q[i*4+3] = f.w * SCALE;
    }

    float o[64];
#pragma unroll
    for (int d = 0; d < 64; d++) o[d] = 0.f;
    float m_i = -1e30f, l_i = 0.f;

    const float* kb = K + (size_t)bh * S_ * HD;
    const float* vb = V + (size_t)bh * S_ * HD;

    for (int kt = 0; kt <= mt; kt++) {
        // cooperative tile load: 1024 float4 per tile, 16 per thread
        const float4* kp = (const float4*)(kb + (size_t)kt * 64 * HD);
        const float4* vp = (const float4*)(vb + (size_t)kt * 64 * HD);
#pragma unroll
        for (int i = 0; i < 16; i++) {
            int idx = t + i * 64;
            ((float4*)Ks)[idx] = kp[idx];
            ((float4*)Vs)[idx] = vp[idx];
        }
        __syncthreads();

        const bool diag = (kt == mt);
        float tmax = -1e30f;
#pragma unroll 2
        for (int j = 0; j < 64; j++) {
            float s;
            if (diag && j > t) {
                s = -1e30f;
            } else {
                float a0 = 0.f, a1 = 0.f, a2 = 0.f, a3 = 0.f;
                const float4* kr = (const float4*)(Ks + j * 64);
#pragma unroll
                for (int d = 0; d < 16; d++) {
                    float4 kk = kr[d];           // broadcast to all lanes
                    a0 += q[d*4+0] * kk.x;
                    a1 += q[d*4+1] * kk.y;
                    a2 += q[d*4+2] * kk.z;
                    a3 += q[d*4+3] * kk.w;
                }
                s = (a0 + a1) + (a2 + a3);
            }
            Ss[t * 64 + ((j + t) & 63)] = s;     // swizzled: conflict-free
            tmax = fmaxf(tmax, s);
        }

        float m_new = fmaxf(m_i, tmax);
        float alpha = expf(m_i - m_new);
        l_i *= alpha;
#pragma unroll
        for (int d = 0; d < 64; d++) o[d] *= alpha;

#pragma unroll 2
        for (int j = 0; j < 64; j++) {
            float p = expf(Ss[t * 64 + ((j + t) & 63)] - m_new);
            l_i += p;
            const float4* vr = (const float4*)(Vs + j * 64);
#pragma unroll
            for (int d = 0; d < 16; d++) {
                float4 vv = vr[d];               // broadcast
                o[d*4+0] += p * vv.x;
                o[d*4+1] += p * vv.y;
                o[d*4+2] += p * vv.z;
                o[d*4+3] += p * vv.w;
            }
        }
        m_i = m_new;
        __syncthreads();
    }

    const float inv = 1.f / l_i;
    const int b = bh >> 4;           // bh / H_
    const int h = bh & (H_ - 1);
    const int s = mt * 64 + t;
    float* op = Oatt + ((size_t)(b * S_ + s)) * D_ + h * HD;
#pragma unroll
    for (int d = 0; d < 64; d += 4) {
        float4 f = make_float4(o[d]*inv, o[d+1]*inv, o[d+2]*inv, o[d+3]*inv);
        *(float4*)(op + d) = f;
    }
}

// ---------------- launch -----------------------------------------------------
extern "C" void kernel_launch(void* const* d_in, const int* in_sizes, int n_in,
                              void* d_out, int out_size)
{
    const float* x  = (const float*)d_in[0];
    const float* Wq = (const float*)d_in[1];
    const float* Wk = (const float*)d_in[2];
    const float* Wv = (const float*)d_in[3];
    const float* Wo = (const float*)d_in[4];
    float* out = (float*)d_out;

    void *pq, *pk, *pv, *patt;
    cudaGetSymbolAddress(&pq,  g_q);
    cudaGetSymbolAddress(&pk,  g_k);
    cudaGetSymbolAddress(&pv,  g_v);
    cudaGetSymbolAddress(&patt, g_att);

    dim3 ggrid(D_ / BN, MTOT / BM);   // (8, 32)
    dim3 gblk(256);

    // Q/K projections with fused RoPE, scattered to [B,H,S,hd]
    gemm_kernel<1, 1><<<ggrid, gblk>>>(x, Wq, (float*)pq);
    gemm_kernel<1, 1><<<ggrid, gblk>>>(x, Wk, (float*)pk);
    gemm_kernel<0, 1><<<ggrid, gblk>>>(x, Wv, (float*)pv);

    // causal flash attention
    dim3 agrid(S_ / 64, B_ * H_);     // (32, 32)
    flash_kernel<<<agrid, 64>>>((const float*)pq, (const float*)pk,
                                (const float*)pv, (float*)patt);

    // output projection
    gemm_kernel<0, 0><<<ggrid, gblk>>>((const float*)patt, Wo, out);
}

// round 3
// speedup vs baseline: 2.5710x; 2.5710x over previous
#include <cuda_runtime.h>
#include <cuda_bf16.h>
#include <cstdint>
#include <math.h>

// ---------------- problem shape ----------------------------------------------
#define B_   2
#define S_   2048
#define D_   1024
#define H_   16
#define HD   64
#define MTOT (B_*S_)          // 4096
#define SCALE 0.125f          // 1/sqrt(64)

// ---------------- baseline-PTX helpers (compile at compute_103) --------------
__device__ __forceinline__ uint32_t smem_u32(const void* p) {
    uint32_t a;
    asm("{ .reg .u64 t; cvta.to.shared.u64 t, %1; cvt.u32.u64 %0, t; }"
        : "=r"(a) : "l"(p));
    return a;
}
#define CP_ASYNC16(dst, src) \
    asm volatile("cp.async.cg.shared.global [%0], [%1], 16;" :: "r"(dst), "l"(src))
#define CP_COMMIT() asm volatile("cp.async.commit_group;" ::: "memory")
#define CP_WAIT1()  asm volatile("cp.async.wait_group 1;" ::: "memory")
#define CP_WAIT0()  asm volatile("cp.async.wait_group 0;" ::: "memory")

__device__ __forceinline__ void ldsm4(uint32_t& r0, uint32_t& r1,
                                      uint32_t& r2, uint32_t& r3, uint32_t a) {
    asm volatile("ldmatrix.sync.aligned.m8n8.x4.shared.b16 {%0,%1,%2,%3}, [%4];"
                 : "=r"(r0), "=r"(r1), "=r"(r2), "=r"(r3) : "r"(a));
}
__device__ __forceinline__ void mma_bf16(float* c,
    uint32_t a0, uint32_t a1, uint32_t a2, uint32_t a3, uint32_t b0, uint32_t b1) {
    asm volatile("mma.sync.aligned.m16n8k16.row.col.f32.bf16.bf16.f32 "
                 "{%0,%1,%2,%3}, {%4,%5,%6,%7}, {%8,%9}, {%0,%1,%2,%3};"
                 : "+f"(c[0]), "+f"(c[1]), "+f"(c[2]), "+f"(c[3])
                 : "r"(a0), "r"(a1), "r"(a2), "r"(a3), "r"(b0), "r"(b1));
}

// ---------------- scratch (device globals; no allocations allowed) ----------
__device__ float g_q[(size_t)B_*H_*S_*HD];     // [B,H,S,hd] fp32
__device__ float g_k[(size_t)B_*H_*S_*HD];
__device__ float g_v[(size_t)B_*H_*S_*HD];
__device__ __nv_bfloat16 g_xh[(size_t)MTOT*D_],  g_xl[(size_t)MTOT*D_];
__device__ __nv_bfloat16 g_wh[(size_t)4*D_*D_],  g_wl[(size_t)4*D_*D_];
__device__ __nv_bfloat16 g_ath[(size_t)MTOT*D_], g_atl[(size_t)MTOT*D_];

// ---------------- fp32 -> (bf16 hi, bf16 lo) split ---------------------------
__global__ void split_kernel(const float* __restrict__ src,
                             __nv_bfloat16* __restrict__ hi,
                             __nv_bfloat16* __restrict__ lo, int n4)
{
    int i = blockIdx.x * blockDim.x + threadIdx.x;
    if (i >= n4) return;
    float4 v = ((const float4*)src)[i];
    __nv_bfloat16 h0 = __float2bfloat16(v.x);
    __nv_bfloat16 h1 = __float2bfloat16(v.y);
    __nv_bfloat16 h2 = __float2bfloat16(v.z);
    __nv_bfloat16 h3 = __float2bfloat16(v.w);
    __nv_bfloat16 l0 = __float2bfloat16(v.x - __bfloat162float(h0));
    __nv_bfloat16 l1 = __float2bfloat16(v.y - __bfloat162float(h1));
    __nv_bfloat16 l2 = __float2bfloat16(v.z - __bfloat162float(h2));
    __nv_bfloat16 l3 = __float2bfloat16(v.w - __bfloat162float(h3));
    __nv_bfloat162 a, b;
    a.x = h0; a.y = h1; b.x = h2; b.y = h3;
    ((__nv_bfloat162*)hi)[2*i]   = a;
    ((__nv_bfloat162*)hi)[2*i+1] = b;
    a.x = l0; a.y = l1; b.x = l2; b.y = l3;
    ((__nv_bfloat162*)lo)[2*i]   = a;
    ((__nv_bfloat162*)lo)[2*i+1] = b;
}

// ---------------- HMMA GEMM: C[m,n] = sum_k A[m,k]*W[n,k] --------------------
// 128x128 tile, BK=32, 8 warps (2x4), m16n8k16 bf16 hi/lo compensated.
#define BKG 32
#define NKI (D_/BKG)       // 32
#define STG 32768          // bytes per stage (4 tiles x 8KB)

// swizzled smem offset for a (row, 16B-chunk) of a 128x32-bf16 tile (64B rows)
__device__ __forceinline__ uint32_t sw_off(int row, int kc) {
    return (uint32_t)((row << 6) + ((kc ^ ((row >> 1) & 3)) << 4));
}

__device__ __forceinline__ void stage_load(
    uint32_t sb, int s, int k0, int tid, int m0, int n0,
    const __nv_bfloat16* __restrict__ Ah, const __nv_bfloat16* __restrict__ Al,
    const __nv_bfloat16* __restrict__ Bh, const __nv_bfloat16* __restrict__ Bl)
{
    const uint32_t base = sb + (uint32_t)s * STG;
#pragma unroll
    for (int p = 0; p < 2; p++) {
        const int gi  = tid + p * 256;   // 0..511
        const int row = gi >> 2;
        const int kc  = gi & 3;
        const uint32_t so = sw_off(row, kc);
        const size_t aoff = (size_t)(m0 + row) * D_ + k0 + kc * 8;
        const size_t boff = (size_t)(n0 + row) * D_ + k0 + kc * 8;
        CP_ASYNC16(base + 0     + so, Ah + aoff);
        CP_ASYNC16(base + 8192  + so, Al + aoff);
        CP_ASYNC16(base + 16384 + so, Bh + boff);
        CP_ASYNC16(base + 24576 + so, Bl + boff);
    }
}

template<int ROPE, int SCATTER>
__global__ __launch_bounds__(256, 1)
void gemm_mma(const __nv_bfloat16* __restrict__ Ah, const __nv_bfloat16* __restrict__ Al,
              const __nv_bfloat16* __restrict__ Bh, const __nv_bfloat16* __restrict__ Bl,
              float* __restrict__ C)
{
    extern __shared__ char smem[];
    const uint32_t sb = smem_u32(smem);
    const int tid  = threadIdx.x;
    const int wid  = tid >> 5;
    const int lane = tid & 31;
    const int m0 = blockIdx.y * 128;
    const int n0 = blockIdx.x * 128;
    const int wm = (wid & 1) * 64;
    const int wn = (wid >> 1) * 32;

    float acc[4][4][4];
#pragma unroll
    for (int a = 0; a < 4; a++)
#pragma unroll
        for (int b = 0; b < 4; b++)
#pragma unroll
            for (int c = 0; c < 4; c++) acc[a][b][c] = 0.f;

    stage_load(sb, 0, 0, tid, m0, n0, Ah, Al, Bh, Bl);
    CP_COMMIT();

    const int g = lane >> 3;
    const int r = lane & 7;

    for (int i = 0; i < NKI; i++) {
        if (i + 1 < NKI) {
            stage_load(sb, (i + 1) & 1, (i + 1) * BKG, tid, m0, n0, Ah, Al, Bh, Bl);
            CP_COMMIT();
            CP_WAIT1();
        } else {
            CP_WAIT0();
        }
        __syncthreads();
        const uint32_t base = sb + (uint32_t)(i & 1) * STG;
#pragma unroll
        for (int h = 0; h < 2; h++) {
            uint32_t ah[4][4], al[4][4], bhf[2][4], blf[2][4];
#pragma unroll
            for (int mi = 0; mi < 4; mi++) {
                const int arow = wm + mi * 16 + (g & 1) * 8 + r;
                const int akc  = h * 2 + (g >> 1);
                const uint32_t so = sw_off(arow, akc);
                ldsm4(ah[mi][0], ah[mi][1], ah[mi][2], ah[mi][3], base + 0 + so);
                ldsm4(al[mi][0], al[mi][1], al[mi][2], al[mi][3], base + 8192 + so);
            }
#pragma unroll
            for (int ng = 0; ng < 2; ng++) {
                const int brow = wn + ng * 16 + (g >> 1) * 8 + r;
                const int bkc  = h * 2 + (g & 1);
                const uint32_t so = sw_off(brow, bkc);
                ldsm4(bhf[ng][0], bhf[ng][1], bhf[ng][2], bhf[ng][3], base + 16384 + so);
                ldsm4(blf[ng][0], blf[ng][1], blf[ng][2], blf[ng][3], base + 24576 + so);
            }
#pragma unroll
            for (int mi = 0; mi < 4; mi++)
#pragma unroll
                for (int ni = 0; ni < 4; ni++) {
                    const uint32_t* bh = &bhf[ni >> 1][(ni & 1) * 2];
                    const uint32_t* bl = &blf[ni >> 1][(ni & 1) * 2];
                    mma_bf16(acc[mi][ni], ah[mi][0], ah[mi][1], ah[mi][2], ah[mi][3], bh[0], bh[1]);
                    mma_bf16(acc[mi][ni], ah[mi][0], ah[mi][1], ah[mi][2], ah[mi][3], bl[0], bl[1]);
                    mma_bf16(acc[mi][ni], al[mi][0], al[mi][1], al[mi][2], al[mi][3], bh[0], bh[1]);
                }
        }
        __syncthreads();
    }

    // ---------------- epilogue (fused RoPE + scatter) -------------------------
    const int tg = lane >> 2;   // row within 8
    const int tq = lane & 3;    // column pair
#pragma unroll
    for (int mi = 0; mi < 4; mi++) {
#pragma unroll
        for (int hf = 0; hf < 2; hf++) {
            const int m    = m0 + wm + mi * 16 + hf * 8 + tg;
            const int spos = m & (S_ - 1);
            const int bb   = m >> 11;
#pragma unroll
            for (int ni = 0; ni < 4; ni++) {
                const int n = n0 + wn + ni * 8 + tq * 2;     // even
                float v1 = acc[mi][ni][hf * 2 + 0];
                float v2 = acc[mi][ni][hf * 2 + 1];
                if (ROPE) {
                    const int d = n & (HD - 1);
                    float theta = powf(10000.0f, -(float)d * (1.0f / (float)HD));
                    float ang = (float)spos * theta;
                    float cc, ss;
                    sincosf(ang, &ss, &cc);
                    float y1 = v1 * cc - v2 * ss;
                    float y2 = v1 * ss + v2 * cc;
                    v1 = y1; v2 = y2;
                }
                if (SCATTER) {
                    const int hh = n >> 6;
                    const int d  = n & (HD - 1);
                    float* p = C + (((size_t)(bb * H_ + hh) * S_) + spos) * HD + d;
                    *(float2*)p = make_float2(v1, v2);
                } else {
                    float* p = C + (size_t)m * D_ + n;
                    *(float2*)p = make_float2(v1, v2);
                }
            }
        }
    }
}

// ---------------- Flash attention (causal), fp32 ----------------------------
// 64 threads/block, one Q row per thread; K/V tiles of 32 rows (16KB smem),
// scores in registers, __expf. Output written as bf16 hi/lo planes.
__global__ __launch_bounds__(64)
void flash_kernel(const float* __restrict__ Q, const float* __restrict__ K,
                  const float* __restrict__ V,
                  __nv_bfloat16* __restrict__ Oh, __nv_bfloat16* __restrict__ Ol)
{
    __shared__ float Ks[32 * 64];
    __shared__ float Vs[32 * 64];

    const int t  = threadIdx.x;
    const int mt = blockIdx.x;
    const int bh = blockIdx.y;
    const int sq = mt * 64 + t;

    float q[64];
    const float* qp = Q + ((size_t)bh * S_ + sq) * HD;
#pragma unroll
    for (int i = 0; i < 16; i++) {
        float4 f = *(const float4*)(qp + i * 4);
        q[i*4+0] = f.x * SCALE; q[i*4+1] = f.y * SCALE;
        q[i*4+2] = f.z * SCALE; q[i*4+3] = f.w * SCALE;
    }

    float o[64];
#pragma unroll
    for (int d = 0; d < 64; d++) o[d] = 0.f;
    float m_i = -1e30f, l_i = 0.f;

    const float* kb = K + (size_t)bh * S_ * HD;
    const float* vb = V + (size_t)bh * S_ * HD;
    const int nkt = 2 * mt + 2;

    for (int kt = 0; kt < nkt; kt++) {
        const float4* kp = (const float4*)(kb + (size_t)kt * 32 * HD);
        const float4* vp = (const float4*)(vb + (size_t)kt * 32 * HD);
#pragma unroll
        for (int i = 0; i < 8; i++) {
            int idx = t + i * 64;
            ((float4*)Ks)[idx] = kp[idx];
            ((float4*)Vs)[idx] = vp[idx];
        }
        __syncthreads();

        float s[32];
        float tmax = -1e30f;
#pragma unroll 4
        for (int j = 0; j < 32; j++) {
            float a0 = 0.f, a1 = 0.f, a2 = 0.f, a3 = 0.f;
            const float4* kr = (const float4*)(Ks + j * 64);
#pragma unroll
            for (int d = 0; d < 16; d++) {
                float4 kk = kr[d];
                a0 += q[d*4+0] * kk.x;
                a1 += q[d*4+1] * kk.y;
                a2 += q[d*4+2] * kk.z;
                a3 += q[d*4+3] * kk.w;
            }
            float sv = (a0 + a1) + (a2 + a3);
            if (kt * 32 + j > sq) sv = -1e30f;      // causal mask
            s[j] = sv;
            tmax = fmaxf(tmax, sv);
        }

        float m_new = fmaxf(m_i, tmax);
        float alpha = __expf(m_i - m_new);
        l_i *= alpha;
#pragma unroll
        for (int d = 0; d < 64; d++) o[d] *= alpha;

#pragma unroll 4
        for (int j = 0; j < 32; j++) {
            float p = __expf(s[j] - m_new);
            l_i += p;
            const float4* vr = (const float4*)(Vs + j * 64);
#pragma unroll
            for (int d = 0; d < 16; d++) {
                float4 vv = vr[d];
                o[d*4+0] += p * vv.x;
                o[d*4+1] += p * vv.y;
                o[d*4+2] += p * vv.z;
                o[d*4+3] += p * vv.w;
            }
        }
        m_i = m_new;
        __syncthreads();
    }

    const float inv = 1.f / l_i;
    const int b = bh >> 4;
    const int h = bh & (H_ - 1);
    const size_t base = ((size_t)(b * S_ + sq)) * D_ + h * HD;
#pragma unroll
    for (int d = 0; d < 64; d += 2) {
        float v0 = o[d] * inv, v1 = o[d+1] * inv;
        __nv_bfloat16 h0 = __float2bfloat16(v0);
        __nv_bfloat16 h1 = __float2bfloat16(v1);
        __nv_bfloat16 l0 = __float2bfloat16(v0 - __bfloat162float(h0));
        __nv_bfloat16 l1 = __float2bfloat16(v1 - __bfloat162float(h1));
        __nv_bfloat162 hp; hp.x = h0; hp.y = h1;
        __nv_bfloat162 lp; lp.x = l0; lp.y = l1;
        *(__nv_bfloat162*)(Oh + base + d) = hp;
        *(__nv_bfloat162*)(Ol + base + d) = lp;
    }
}

// ---------------- launch -----------------------------------------------------
extern "C" void kernel_launch(void* const* d_in, const int* in_sizes, int n_in,
                              void* d_out, int out_size)
{
    const float* x  = (const float*)d_in[0];
    const float* W[4] = { (const float*)d_in[1], (const float*)d_in[2],
                          (const float*)d_in[3], (const float*)d_in[4] };
    float* out = (float*)d_out;

    void *pq, *pk, *pv, *pxh, *pxl, *pwh, *pwl, *path, *patl;
    cudaGetSymbolAddress(&pq,  g_q);
    cudaGetSymbolAddress(&pk,  g_k);
    cudaGetSymbolAddress(&pv,  g_v);
    cudaGetSymbolAddress(&pxh, g_xh);
    cudaGetSymbolAddress(&pxl, g_xl);
    cudaGetSymbolAddress(&pwh, g_wh);
    cudaGetSymbolAddress(&pwl, g_wl);
    cudaGetSymbolAddress(&path, g_ath);
    cudaGetSymbolAddress(&patl, g_atl);

    const int SMEM_BYTES = 2 * STG;   // 64 KB
    cudaFuncSetAttribute(gemm_mma<1,1>, cudaFuncAttributeMaxDynamicSharedMemorySize, SMEM_BYTES);
    cudaFuncSetAttribute(gemm_mma<0,1>, cudaFuncAttributeMaxDynamicSharedMemorySize, SMEM_BYTES);
    cudaFuncSetAttribute(gemm_mma<0,0>, cudaFuncAttributeMaxDynamicSharedMemorySize, SMEM_BYTES);

    __nv_bfloat16* xh = (__nv_bfloat16*)pxh;
    __nv_bfloat16* xl = (__nv_bfloat16*)pxl;
    __nv_bfloat16* wh = (__nv_bfloat16*)pwh;
    __nv_bfloat16* wl = (__nv_bfloat16*)pwl;
    __nv_bfloat16* ath = (__nv_bfloat16*)path;
    __nv_bfloat16* atl = (__nv_bfloat16*)patl;

    // fp32 -> bf16 hi/lo splits
    {
        int n4 = MTOT * D_ / 4;
        split_kernel<<<(n4 + 255)/256, 256>>>(x, xh, xl, n4);
        int w4 = D_ * D_ / 4;
        for (int w = 0; w < 4; w++)
            split_kernel<<<(w4 + 255)/256, 256>>>(W[w], wh + (size_t)w*D_*D_, wl + (size_t)w*D_*D_, w4);
    }

    dim3 ggrid(D_ / 128, MTOT / 128);   // (8, 32)

    gemm_mma<1,1><<<ggrid, 256, SMEM_BYTES>>>(xh, xl, wh + 0*(size_t)D_*D_, wl + 0*(size_t)D_*D_, (float*)pq);
    gemm_mma<1,1><<<ggrid, 256, SMEM_BYTES>>>(xh, xl, wh + 1*(size_t)D_*D_, wl + 1*(size_t)D_*D_, (float*)pk);
    gemm_mma<0,1><<<ggrid, 256, SMEM_BYTES>>>(xh, xl, wh + 2*(size_t)D_*D_, wl + 2*(size_t)D_*D_, (float*)pv);

    dim3 agrid(S_ / 64, B_ * H_);       // (32, 32)
    flash_kernel<<<agrid, 64>>>((const float*)pq, (const float*)pk, (const float*)pv, ath, atl);

    gemm_mma<0,0><<<ggrid, 256, SMEM_BYTES>>>(ath, atl, wh + 3*(size_t)D_*D_, wl + 3*(size_t)D_*D_, out);
}

// round 4
// speedup vs baseline: 3.7845x; 1.4720x over previous
#include <cuda_runtime.h>
#include <cuda_bf16.h>
#include <cstdint>
#include <math.h>

// ---------------- problem shape ----------------------------------------------
#define B_   2
#define S_   2048
#define D_   1024
#define H_   16
#define HD   64
#define MTOT (B_*S_)          // 4096
#define SCALE 0.125f          // 1/sqrt(64), exact power of two

// ---------------- baseline-PTX helpers (compile at compute_103) --------------
__device__ __forceinline__ uint32_t smem_u32(const void* p) {
    uint32_t a;
    asm("{ .reg .u64 t; cvta.to.shared.u64 t, %1; cvt.u32.u64 %0, t; }"
        : "=r"(a) : "l"(p));
    return a;
}
#define CP_ASYNC16(dst, src) \
    asm volatile("cp.async.cg.shared.global [%0], [%1], 16;" :: "r"(dst), "l"(src))
#define CP_COMMIT() asm volatile("cp.async.commit_group;" ::: "memory")
#define CP_WAIT1()  asm volatile("cp.async.wait_group 1;" ::: "memory")
#define CP_WAIT0()  asm volatile("cp.async.wait_group 0;" ::: "memory")

__device__ __forceinline__ void ldsm4(uint32_t& r0, uint32_t& r1,
                                      uint32_t& r2, uint32_t& r3, uint32_t a) {
    asm volatile("ldmatrix.sync.aligned.m8n8.x4.shared.b16 {%0,%1,%2,%3}, [%4];"
                 : "=r"(r0), "=r"(r1), "=r"(r2), "=r"(r3) : "r"(a));
}
__device__ __forceinline__ void ldsm4t(uint32_t& r0, uint32_t& r1,
                                       uint32_t& r2, uint32_t& r3, uint32_t a) {
    asm volatile("ldmatrix.sync.aligned.m8n8.x4.trans.shared.b16 {%0,%1,%2,%3}, [%4];"
                 : "=r"(r0), "=r"(r1), "=r"(r2), "=r"(r3) : "r"(a));
}
__device__ __forceinline__ void mma_bf16(float* c,
    uint32_t a0, uint32_t a1, uint32_t a2, uint32_t a3, uint32_t b0, uint32_t b1) {
    asm volatile("mma.sync.aligned.m16n8k16.row.col.f32.bf16.bf16.f32 "
                 "{%0,%1,%2,%3}, {%4,%5,%6,%7}, {%8,%9}, {%0,%1,%2,%3};"
                 : "+f"(c[0]), "+f"(c[1]), "+f"(c[2]), "+f"(c[3])
                 : "r"(a0), "r"(a1), "r"(a2), "r"(a3), "r"(b0), "r"(b1));
}
__device__ __forceinline__ uint32_t pack_bf2(float lo, float hi) {
    __nv_bfloat162 t = __floats2bfloat162_rn(lo, hi);   // x=lo (low half)
    return *(uint32_t*)&t;
}

// ---------------- scratch (device globals; no allocations allowed) ----------
__device__ __nv_bfloat16 g_qh[(size_t)B_*H_*S_*HD], g_ql[(size_t)B_*H_*S_*HD];
__device__ __nv_bfloat16 g_kh[(size_t)B_*H_*S_*HD], g_kl[(size_t)B_*H_*S_*HD];
__device__ __nv_bfloat16 g_vh[(size_t)B_*H_*S_*HD], g_vl[(size_t)B_*H_*S_*HD];
__device__ __nv_bfloat16 g_xh[(size_t)MTOT*D_],  g_xl[(size_t)MTOT*D_];
__device__ __nv_bfloat16 g_wh[(size_t)4*D_*D_],  g_wl[(size_t)4*D_*D_];
__device__ __nv_bfloat16 g_ath[(size_t)MTOT*D_], g_atl[(size_t)MTOT*D_];

// ---------------- fp32 -> (bf16 hi, bf16 lo) split ---------------------------
__global__ void split_kernel(const float* __restrict__ src,
                             __nv_bfloat16* __restrict__ hi,
                             __nv_bfloat16* __restrict__ lo, int n4)
{
    int i = blockIdx.x * blockDim.x + threadIdx.x;
    if (i >= n4) return;
    float4 v = ((const float4*)src)[i];
    __nv_bfloat16 h0 = __float2bfloat16(v.x);
    __nv_bfloat16 h1 = __float2bfloat16(v.y);
    __nv_bfloat16 h2 = __float2bfloat16(v.z);
    __nv_bfloat16 h3 = __float2bfloat16(v.w);
    __nv_bfloat16 l0 = __float2bfloat16(v.x - __bfloat162float(h0));
    __nv_bfloat16 l1 = __float2bfloat16(v.y - __bfloat162float(h1));
    __nv_bfloat16 l2 = __float2bfloat16(v.z - __bfloat162float(h2));
    __nv_bfloat16 l3 = __float2bfloat16(v.w - __bfloat162float(h3));
    __nv_bfloat162 a, b;
    a.x = h0; a.y = h1; b.x = h2; b.y = h3;
    ((__nv_bfloat162*)hi)[2*i]   = a;
    ((__nv_bfloat162*)hi)[2*i+1] = b;
    a.x = l0; a.y = l1; b.x = l2; b.y = l3;
    ((__nv_bfloat162*)lo)[2*i]   = a;
    ((__nv_bfloat162*)lo)[2*i+1] = b;
}

// ---------------- HMMA GEMM: C[m,n] = sum_k A[m,k]*W[n,k] --------------------
#define BKG 32
#define NKI (D_/BKG)       // 32
#define STG 32768          // bytes per stage

__device__ __forceinline__ uint32_t sw_off(int row, int kc) {
    return (uint32_t)((row << 6) + ((kc ^ ((row >> 1) & 3)) << 4));
}

__device__ __forceinline__ void stage_load(
    uint32_t sb, int s, int k0, int tid, int m0, int n0,
    const __nv_bfloat16* __restrict__ Ah, const __nv_bfloat16* __restrict__ Al,
    const __nv_bfloat16* __restrict__ Bh, const __nv_bfloat16* __restrict__ Bl)
{
    const uint32_t base = sb + (uint32_t)s * STG;
#pragma unroll
    for (int p = 0; p < 2; p++) {
        const int gi  = tid + p * 256;
        const int row = gi >> 2;
        const int kc  = gi & 3;
        const uint32_t so = sw_off(row, kc);
        const size_t aoff = (size_t)(m0 + row) * D_ + k0 + kc * 8;
        const size_t boff = (size_t)(n0 + row) * D_ + k0 + kc * 8;
        CP_ASYNC16(base + 0     + so, Ah + aoff);
        CP_ASYNC16(base + 8192  + so, Al + aoff);
        CP_ASYNC16(base + 16384 + so, Bh + boff);
        CP_ASYNC16(base + 24576 + so, Bl + boff);
    }
}

// OUTK: 0 = fp32 [M,N] to Cf; 1 = bf16 hi/lo scatter [B,H,S,hd] to Ch/Cl
template<int ROPE, int QSC, int OUTK>
__global__ __launch_bounds__(256, 1)
void gemm_mma(const __nv_bfloat16* __restrict__ Ah, const __nv_bfloat16* __restrict__ Al,
              const __nv_bfloat16* __restrict__ Bh, const __nv_bfloat16* __restrict__ Bl,
              float* __restrict__ Cf,
              __nv_bfloat16* __restrict__ Ch, __nv_bfloat16* __restrict__ Cl)
{
    extern __shared__ char smem[];
    const uint32_t sb = smem_u32(smem);
    const int tid  = threadIdx.x;
    const int wid  = tid >> 5;
    const int lane = tid & 31;
    const int m0 = blockIdx.y * 128;
    const int n0 = blockIdx.x * 128;
    const int wm = (wid & 1) * 64;
    const int wn = (wid >> 1) * 32;

    float acc[4][4][4];
#pragma unroll
    for (int a = 0; a < 4; a++)
#pragma unroll
        for (int b = 0; b < 4; b++)
#pragma unroll
            for (int c = 0; c < 4; c++) acc[a][b][c] = 0.f;

    stage_load(sb, 0, 0, tid, m0, n0, Ah, Al, Bh, Bl);
    CP_COMMIT();

    const int g = lane >> 3;
    const int r = lane & 7;

    for (int i = 0; i < NKI; i++) {
        if (i + 1 < NKI) {
            stage_load(sb, (i + 1) & 1, (i + 1) * BKG, tid, m0, n0, Ah, Al, Bh, Bl);
            CP_COMMIT();
            CP_WAIT1();
        } else {
            CP_WAIT0();
        }
        __syncthreads();
        const uint32_t base = sb + (uint32_t)(i & 1) * STG;
#pragma unroll
        for (int h = 0; h < 2; h++) {
            uint32_t ah[4][4], al[4][4], bhf[2][4], blf[2][4];
#pragma unroll
            for (int mi = 0; mi < 4; mi++) {
                const int arow = wm + mi * 16 + (g & 1) * 8 + r;
                const int akc  = h * 2 + (g >> 1);
                const uint32_t so = sw_off(arow, akc);
                ldsm4(ah[mi][0], ah[mi][1], ah[mi][2], ah[mi][3], base + 0 + so);
                ldsm4(al[mi][0], al[mi][1], al[mi][2], al[mi][3], base + 8192 + so);
            }
#pragma unroll
            for (int ng = 0; ng < 2; ng++) {
                const int brow = wn + ng * 16 + (g >> 1) * 8 + r;
                const int bkc  = h * 2 + (g & 1);
                const uint32_t so = sw_off(brow, bkc);
                ldsm4(bhf[ng][0], bhf[ng][1], bhf[ng][2], bhf[ng][3], base + 16384 + so);
                ldsm4(blf[ng][0], blf[ng][1], blf[ng][2], blf[ng][3], base + 24576 + so);
            }
#pragma unroll
            for (int mi = 0; mi < 4; mi++)
#pragma unroll
                for (int ni = 0; ni < 4; ni++) {
                    const uint32_t* bh = &bhf[ni >> 1][(ni & 1) * 2];
                    const uint32_t* bl = &blf[ni >> 1][(ni & 1) * 2];
                    mma_bf16(acc[mi][ni], ah[mi][0], ah[mi][1], ah[mi][2], ah[mi][3], bh[0], bh[1]);
                    mma_bf16(acc[mi][ni], ah[mi][0], ah[mi][1], ah[mi][2], ah[mi][3], bl[0], bl[1]);
                    mma_bf16(acc[mi][ni], al[mi][0], al[mi][1], al[mi][2], al[mi][3], bh[0], bh[1]);
                }
        }
        __syncthreads();
    }

    // ---------------- epilogue (fused RoPE/scale + split/scatter) -------------
    const int tg = lane >> 2;
    const int tq = lane & 3;
#pragma unroll
    for (int mi = 0; mi < 4; mi++) {
#pragma unroll
        for (int hf = 0; hf < 2; hf++) {
            const int m    = m0 + wm + mi * 16 + hf * 8 + tg;
            const int spos = m & (S_ - 1);
            const int bb   = m >> 11;
#pragma unroll
            for (int ni = 0; ni < 4; ni++) {
                const int n = n0 + wn + ni * 8 + tq * 2;     // even
                float v1 = acc[mi][ni][hf * 2 + 0];
                float v2 = acc[mi][ni][hf * 2 + 1];
                if (ROPE) {
                    const int d = n & (HD - 1);
                    float theta = powf(10000.0f, -(float)d * (1.0f / (float)HD));
                    float ang = (float)spos * theta;
                    float cc, ss;
                    sincosf(ang, &ss, &cc);
                    float y1 = v1 * cc - v2 * ss;
                    float y2 = v1 * ss + v2 * cc;
                    v1 = y1; v2 = y2;
                }
                if (QSC) { v1 *= SCALE; v2 *= SCALE; }
                if (OUTK == 1) {
                    const int hh = n >> 6;
                    const int d  = n & (HD - 1);
                    const size_t idx = (((size_t)(bb * H_ + hh) * S_) + spos) * HD + d;
                    __nv_bfloat16 h1 = __float2bfloat16(v1);
                    __nv_bfloat16 h2 = __float2bfloat16(v2);
                    __nv_bfloat16 l1 = __float2bfloat16(v1 - __bfloat162float(h1));
                    __nv_bfloat16 l2 = __float2bfloat16(v2 - __bfloat162float(h2));
                    __nv_bfloat162 hp; hp.x = h1; hp.y = h2;
                    __nv_bfloat162 lp; lp.x = l1; lp.y = l2;
                    *(__nv_bfloat162*)(Ch + idx) = hp;
                    *(__nv_bfloat162*)(Cl + idx) = lp;
                } else {
                    float* p = Cf + (size_t)m * D_ + n;
                    *(float2*)p = make_float2(v1, v2);
                }
            }
        }
    }
}

// ---------------- HMMA flash attention (causal) ------------------------------
// 128 threads (4 warps), Q tile 64 rows (16/warp), K/V tiles 64 rows,
// double-buffered cp.async. Compensated bf16 hi/lo on QK and PV.
// smem: QH[8K] QL[8K] | stage0: KH KL VH VL (8K each) | stage1 same = 80KB.
#define FQ_OFF  0u
#define FQL_OFF 8192u
#define FST_OFF 16384u
#define FSTG    32768u
#define FSMEM   (16384 + 2*32768)

__device__ __forceinline__ uint32_t fsw(int row, int c) {   // 128B rows, 8 chunks
    return (uint32_t)(row * 128 + ((c ^ (row & 7)) << 4));
}

__device__ __forceinline__ void fa_stage(
    uint32_t base, const __nv_bfloat16* kh, const __nv_bfloat16* kl,
    const __nv_bfloat16* vh, const __nv_bfloat16* vl, int s0, int tid)
{
#pragma unroll
    for (int p = 0; p < 4; p++) {
        const int gi  = tid + p * 128;       // 0..511
        const int row = gi >> 3;
        const int c   = gi & 7;
        const uint32_t off = fsw(row, c);
        const size_t g = (size_t)(s0 + row) * HD + c * 8;
        CP_ASYNC16(base + 0u     + off, kh + g);
        CP_ASYNC16(base + 8192u  + off, kl + g);
        CP_ASYNC16(base + 16384u + off, vh + g);
        CP_ASYNC16(base + 24576u + off, vl + g);
    }
}

__global__ __launch_bounds__(128)
void flash_mma(const __nv_bfloat16* __restrict__ Qh, const __nv_bfloat16* __restrict__ Ql,
               const __nv_bfloat16* __restrict__ Kh, const __nv_bfloat16* __restrict__ Kl,
               const __nv_bfloat16* __restrict__ Vh, const __nv_bfloat16* __restrict__ Vl,
               __nv_bfloat16* __restrict__ Oh, __nv_bfloat16* __restrict__ Ol)
{
    extern __shared__ char smem[];
    const uint32_t sb = smem_u32(smem);
    const int tid  = threadIdx.x;
    const int wid  = tid >> 5;
    const int lane = tid & 31;
    const int bh = blockIdx.y;
    const int mt = (int)gridDim.x - 1 - (int)blockIdx.x;   // big tiles first
    const int nkt = mt + 1;

    const __nv_bfloat16* qhb = Qh + ((size_t)bh * S_) * HD;
    const __nv_bfloat16* qlb = Ql + ((size_t)bh * S_) * HD;
    const __nv_bfloat16* khb_ = Kh + ((size_t)bh * S_) * HD;
    const __nv_bfloat16* klb_ = Kl + ((size_t)bh * S_) * HD;
    const __nv_bfloat16* vhb_ = Vh + ((size_t)bh * S_) * HD;
    const __nv_bfloat16* vlb_ = Vl + ((size_t)bh * S_) * HD;

    // cp.async Q tile (rows mt*64..+63) + stage 0
#pragma unroll
    for (int p = 0; p < 4; p++) {
        const int gi  = tid + p * 128;
        const int row = gi >> 3;
        const int c   = gi & 7;
        const uint32_t off = fsw(row, c);
        const size_t g = (size_t)(mt * 64 + row) * HD + c * 8;
        CP_ASYNC16(sb + FQ_OFF  + off, qhb + g);
        CP_ASYNC16(sb + FQL_OFF + off, qlb + g);
    }
    fa_stage(sb + FST_OFF, khb_, klb_, vhb_, vlb_, 0, tid);
    CP_COMMIT();

    uint32_t qhf[4][4], qlf[4][4];
    float o[8][4];
#pragma unroll
    for (int a = 0; a < 8; a++)
#pragma unroll
        for (int b = 0; b < 4; b++) o[a][b] = 0.f;
    float m0r = -1e30f, m1r = -1e30f, l0r = 0.f, l1r = 0.f;

    const int grp = lane >> 3;
    const int rr  = lane & 7;

    for (int kt = 0; kt < nkt; kt++) {
        if (kt + 1 < nkt) {
            fa_stage(sb + FST_OFF + (uint32_t)((kt + 1) & 1) * FSTG,
                     khb_, klb_, vhb_, vlb_, (kt + 1) * 64, tid);
            CP_COMMIT();
            CP_WAIT1();
        } else {
            CP_WAIT0();
        }
        __syncthreads();

        if (kt == 0) {
            // Q A-frags: per kc one x4 (tiles: (0,kc2),(8,kc2),(0,kc2+1),(8,kc2+1))
#pragma unroll
            for (int kc = 0; kc < 4; kc++) {
                const int row = wid * 16 + (grp & 1) * 8 + rr;
                const int c   = kc * 2 + (grp >> 1);
                const uint32_t off = fsw(row, c);
                ldsm4(qhf[kc][0], qhf[kc][1], qhf[kc][2], qhf[kc][3], sb + FQ_OFF + off);
                ldsm4(qlf[kc][0], qlf[kc][1], qlf[kc][2], qlf[kc][3], sb + FQL_OFF + off);
            }
        }

        const uint32_t st = sb + FST_OFF + (uint32_t)(kt & 1) * FSTG;

        // ---- scores S = Q K^T --------------------------------------------
        float c[8][4];
#pragma unroll
        for (int a = 0; a < 8; a++)
#pragma unroll
            for (int b = 0; b < 4; b++) c[a][b] = 0.f;

#pragma unroll
        for (int nt = 0; nt < 8; nt++) {
            const int j = nt * 8 + rr;
            uint32_t kb0[4], kb1[4], lb0[4], lb1[4];
            // chunks 0..3 then 4..7 (each x4 -> b0,b1 for two kc)
            ldsm4(kb0[0], kb0[1], kb0[2], kb0[3], st + 0u    + fsw(j, 0 + grp));
            ldsm4(kb1[0], kb1[1], kb1[2], kb1[3], st + 0u    + fsw(j, 4 + grp));
            ldsm4(lb0[0], lb0[1], lb0[2], lb0[3], st + 8192u + fsw(j, 0 + grp));
            ldsm4(lb1[0], lb1[1], lb1[2], lb1[3], st + 8192u + fsw(j, 4 + grp));
            // kc 0,1 from kb0; kc 2,3 from kb1
            mma_bf16(c[nt], qhf[0][0], qhf[0][1], qhf[0][2], qhf[0][3], kb0[0], kb0[1]);
            mma_bf16(c[nt], qhf[0][0], qhf[0][1], qhf[0][2], qhf[0][3], lb0[0], lb0[1]);
            mma_bf16(c[nt], qlf[0][0], qlf[0][1], qlf[0][2], qlf[0][3], kb0[0], kb0[1]);
            mma_bf16(c[nt], qhf[1][0], qhf[1][1], qhf[1][2], qhf[1][3], kb0[2], kb0[3]);
            mma_bf16(c[nt], qhf[1][0], qhf[1][1], qhf[1][2], qhf[1][3], lb0[2], lb0[3]);
            mma_bf16(c[nt], qlf[1][0], qlf[1][1], qlf[1][2], qlf[1][3], kb0[2], kb0[3]);
            mma_bf16(c[nt], qhf[2][0], qhf[2][1], qhf[2][2], qhf[2][3], kb1[0], kb1[1]);
            mma_bf16(c[nt], qhf[2][0], qhf[2][1], qhf[2][2], qhf[2][3], lb1[0], lb1[1]);
            mma_bf16(c[nt], qlf[2][0], qlf[2][1], qlf[2][2], qlf[2][3], kb1[0], kb1[1]);
            mma_bf16(c[nt], qhf[3][0], qhf[3][1], qhf[3][2], qhf[3][3], kb1[2], kb1[3]);
            mma_bf16(c[nt], qhf[3][0], qhf[3][1], qhf[3][2], qhf[3][3], lb1[2], lb1[3]);
            mma_bf16(c[nt], qlf[3][0], qlf[3][1], qlf[3][2], qlf[3][3], kb1[2], kb1[3]);
        }

        // ---- causal mask on diagonal tile --------------------------------
        if (kt == mt) {
            const int i0 = wid * 16 + (lane >> 2);
#pragma unroll
            for (int nt = 0; nt < 8; nt++) {
                const int j0 = nt * 8 + (lane & 3) * 2;
                if (j0     > i0)     c[nt][0] = -1e30f;
                if (j0 + 1 > i0)     c[nt][1] = -1e30f;
                if (j0     > i0 + 8) c[nt][2] = -1e30f;
                if (j0 + 1 > i0 + 8) c[nt][3] = -1e30f;
            }
        }

        // ---- online softmax ----------------------------------------------
        float t0 = -1e30f, t1 = -1e30f;
#pragma unroll
        for (int nt = 0; nt < 8; nt++) {
            t0 = fmaxf(t0, fmaxf(c[nt][0], c[nt][1]));
            t1 = fmaxf(t1, fmaxf(c[nt][2], c[nt][3]));
        }
        t0 = fmaxf(t0, __shfl_xor_sync(0xffffffffu, t0, 1));
        t0 = fmaxf(t0, __shfl_xor_sync(0xffffffffu, t0, 2));
        t1 = fmaxf(t1, __shfl_xor_sync(0xffffffffu, t1, 1));
        t1 = fmaxf(t1, __shfl_xor_sync(0xffffffffu, t1, 2));
        const float mn0 = fmaxf(m0r, t0);
        const float mn1 = fmaxf(m1r, t1);
        const float al0 = __expf(m0r - mn0);
        const float al1 = __expf(m1r - mn1);
        m0r = mn0; m1r = mn1;

        float s0 = 0.f, s1 = 0.f;
#pragma unroll
        for (int nt = 0; nt < 8; nt++) {
            c[nt][0] = __expf(c[nt][0] - mn0);
            c[nt][1] = __expf(c[nt][1] - mn0);
            c[nt][2] = __expf(c[nt][2] - mn1);
            c[nt][3] = __expf(c[nt][3] - mn1);
            s0 += c[nt][0] + c[nt][1];
            s1 += c[nt][2] + c[nt][3];
        }
        s0 += __shfl_xor_sync(0xffffffffu, s0, 1);
        s0 += __shfl_xor_sync(0xffffffffu, s0, 2);
        s1 += __shfl_xor_sync(0xffffffffu, s1, 1);
        s1 += __shfl_xor_sync(0xffffffffu, s1, 2);
        l0r = l0r * al0 + s0;
        l1r = l1r * al1 + s1;

#pragma unroll
        for (int nt = 0; nt < 8; nt++) {
            o[nt][0] *= al0; o[nt][1] *= al0;
            o[nt][2] *= al1; o[nt][3] *= al1;
        }

        // ---- P -> bf16 hi/lo A-frags (pure register repack) --------------
        uint32_t ph[4][4], pl[4][4];
#pragma unroll
        for (int kc = 0; kc < 4; kc++) {
            const float* p0 = c[2*kc];
            const float* p1 = c[2*kc+1];
            ph[kc][0] = pack_bf2(p0[0], p0[1]);
            ph[kc][1] = pack_bf2(p0[2], p0[3]);
            ph[kc][2] = pack_bf2(p1[0], p1[1]);
            ph[kc][3] = pack_bf2(p1[2], p1[3]);
            __nv_bfloat162 h;
            *(uint32_t*)&h = ph[kc][0];
            pl[kc][0] = pack_bf2(p0[0]-__bfloat162float(h.x), p0[1]-__bfloat162float(h.y));
            *(uint32_t*)&h = ph[kc][1];
            pl[kc][1] = pack_bf2(p0[2]-__bfloat162float(h.x), p0[3]-__bfloat162float(h.y));
            *(uint32_t*)&h = ph[kc][2];
            pl[kc][2] = pack_bf2(p1[0]-__bfloat162float(h.x), p1[1]-__bfloat162float(h.y));
            *(uint32_t*)&h = ph[kc][3];
            pl[kc][3] = pack_bf2(p1[2]-__bfloat162float(h.x), p1[3]-__bfloat162float(h.y));
        }

        // ---- O += P V (V via ldmatrix.trans) -----------------------------
#pragma unroll
        for (int ntp = 0; ntp < 4; ntp++) {
#pragma unroll
            for (int kc = 0; kc < 4; kc++) {
                const int row = kc * 16 + (grp & 1) * 8 + rr;
                const int ch  = ntp * 2 + (grp >> 1);
                const uint32_t off = fsw(row, ch);
                uint32_t vh0, vh1, vh2, vh3, vl0, vl1, vl2, vl3;
                ldsm4t(vh0, vh1, vh2, vh3, st + 16384u + off);
                ldsm4t(vl0, vl1, vl2, vl3, st + 24576u + off);
                mma_bf16(o[2*ntp],   ph[kc][0], ph[kc][1], ph[kc][2], ph[kc][3], vh0, vh1);
                mma_bf16(o[2*ntp],   ph[kc][0], ph[kc][1], ph[kc][2], ph[kc][3], vl0, vl1);
                mma_bf16(o[2*ntp],   pl[kc][0], pl[kc][1], pl[kc][2], pl[kc][3], vh0, vh1);
                mma_bf16(o[2*ntp+1], ph[kc][0], ph[kc][1], ph[kc][2], ph[kc][3], vh2, vh3);
                mma_bf16(o[2*ntp+1], ph[kc][0], ph[kc][1], ph[kc][2], ph[kc][3], vl2, vl3);
                mma_bf16(o[2*ntp+1], pl[kc][0], pl[kc][1], pl[kc][2], pl[kc][3], vh2, vh3);
            }
        }
        __syncthreads();
    }

    // ---- finalize + write bf16 hi/lo [B,S,D] --------------------------------
    const float inv0 = 1.f / l0r;
    const float inv1 = 1.f / l1r;
    const int b = bh >> 4;
    const int h = bh & (H_ - 1);
    const int sq0 = mt * 64 + wid * 16 + (lane >> 2);
    const size_t base0 = ((size_t)(b * S_ + sq0)) * D_ + h * HD;
    const size_t base1 = base0 + (size_t)8 * D_;
#pragma unroll
    for (int nt = 0; nt < 8; nt++) {
        const int col = nt * 8 + (lane & 3) * 2;
        {
            float v0 = o[nt][0] * inv0, v1 = o[nt][1] * inv0;
            __nv_bfloat16 h0 = __float2bfloat16(v0);
            __nv_bfloat16 h1 = __float2bfloat16(v1);
            __nv_bfloat16 l0 = __float2bfloat16(v0 - __bfloat162float(h0));
            __nv_bfloat16 l1 = __float2bfloat16(v1 - __bfloat162float(h1));
            __nv_bfloat162 hp; hp.x = h0; hp.y = h1;
            __nv_bfloat162 lp; lp.x = l0; lp.y = l1;
            *(__nv_bfloat162*)(Oh + base0 + col) = hp;
            *(__nv_bfloat162*)(Ol + base0 + col) = lp;
        }
        {
            float v0 = o[nt][2] * inv1, v1 = o[nt][3] * inv1;
            __nv_bfloat16 h0 = __float2bfloat16(v0);
            __nv_bfloat16 h1 = __float2bfloat16(v1);
            __nv_bfloat16 l0 = __float2bfloat16(v0 - __bfloat162float(h0));
            __nv_bfloat16 l1 = __float2bfloat16(v1 - __bfloat162float(h1));
            __nv_bfloat162 hp; hp.x = h0; hp.y = h1;
            __nv_bfloat162 lp; lp.x = l0; lp.y = l1;
            *(__nv_bfloat162*)(Oh + base1 + col) = hp;
            *(__nv_bfloat162*)(Ol + base1 + col) = lp;
        }
    }
}

// ---------------- launch -----------------------------------------------------
extern "C" void kernel_launch(void* const* d_in, const int* in_sizes, int n_in,
                              void* d_out, int out_size)
{
    const float* x  = (const float*)d_in[0];
    const float* W[4] = { (const float*)d_in[1], (const float*)d_in[2],
                          (const float*)d_in[3], (const float*)d_in[4] };
    float* out = (float*)d_out;

    void *pqh, *pql, *pkh, *pkl, *pvh, *pvl, *pxh, *pxl, *pwh, *pwl, *path, *patl;
    cudaGetSymbolAddress(&pqh, g_qh);  cudaGetSymbolAddress(&pql, g_ql);
    cudaGetSymbolAddress(&pkh, g_kh);  cudaGetSymbolAddress(&pkl, g_kl);
    cudaGetSymbolAddress(&pvh, g_vh);  cudaGetSymbolAddress(&pvl, g_vl);
    cudaGetSymbolAddress(&pxh, g_xh);  cudaGetSymbolAddress(&pxl, g_xl);
    cudaGetSymbolAddress(&pwh, g_wh);  cudaGetSymbolAddress(&pwl, g_wl);
    cudaGetSymbolAddress(&path, g_ath); cudaGetSymbolAddress(&patl, g_atl);

    const int GSMEM = 2 * STG;   // 64 KB
    cudaFuncSetAttribute(gemm_mma<1,1,1>, cudaFuncAttributeMaxDynamicSharedMemorySize, GSMEM);
    cudaFuncSetAttribute(gemm_mma<1,0,1>, cudaFuncAttributeMaxDynamicSharedMemorySize, GSMEM);
    cudaFuncSetAttribute(gemm_mma<0,0,1>, cudaFuncAttributeMaxDynamicSharedMemorySize, GSMEM);
    cudaFuncSetAttribute(gemm_mma<0,0,0>, cudaFuncAttributeMaxDynamicSharedMemorySize, GSMEM);
    cudaFuncSetAttribute(flash_mma, cudaFuncAttributeMaxDynamicSharedMemorySize, FSMEM);

    __nv_bfloat16* xh = (__nv_bfloat16*)pxh;
    __nv_bfloat16* xl = (__nv_bfloat16*)pxl;
    __nv_bfloat16* wh = (__nv_bfloat16*)pwh;
    __nv_bfloat16* wl = (__nv_bfloat16*)pwl;

    // fp32 -> bf16 hi/lo splits
    {
        int n4 = MTOT * D_ / 4;
        split_kernel<<<(n4 + 255)/256, 256>>>(x, xh, xl, n4);
        int w4 = D_ * D_ / 4;
        for (int w = 0; w < 4; w++)
            split_kernel<<<(w4 + 255)/256, 256>>>(W[w], wh + (size_t)w*D_*D_, wl + (size_t)w*D_*D_, w4);
    }

    dim3 ggrid(D_ / 128, MTOT / 128);   // (8, 32)

    // projections -> bf16 hi/lo [B,H,S,hd]; Q with RoPE+scale, K with RoPE
    gemm_mma<1,1,1><<<ggrid, 256, GSMEM>>>(xh, xl, wh + 0*(size_t)D_*D_, wl + 0*(size_t)D_*D_,
                                           nullptr, (__nv_bfloat16*)pqh, (__nv_bfloat16*)pql);
    gemm_mma<1,0,1><<<ggrid, 256, GSMEM>>>(xh, xl, wh + 1*(size_t)D_*D_, wl + 1*(size_t)D_*D_,
                                           nullptr, (__nv_bfloat16*)pkh, (__nv_bfloat16*)pkl);
    gemm_mma<0,0,1><<<ggrid, 256, GSMEM>>>(xh, xl, wh + 2*(size_t)D_*D_, wl + 2*(size_t)D_*D_,
                                           nullptr, (__nv_bfloat16*)pvh, (__nv_bfloat16*)pvl);

    // tensor-core causal flash attention -> bf16 hi/lo [B,S,D]
    dim3 agrid(S_ / 64, B_ * H_);       // (32, 32)
    flash_mma<<<agrid, 128, FSMEM>>>((const __nv_bfloat16*)pqh, (const __nv_bfloat16*)pql,
                                     (const __nv_bfloat16*)pkh, (const __nv_bfloat16*)pkl,
                                     (const __nv_bfloat16*)pvh, (const __nv_bfloat16*)pvl,
                                     (__nv_bfloat16*)path, (__nv_bfloat16*)patl);

    // output projection -> d_out (fp32)
    gemm_mma<0,0,0><<<ggrid, 256, GSMEM>>>((const __nv_bfloat16*)path, (const __nv_bfloat16*)patl,
                                           wh + 3*(size_t)D_*D_, wl + 3*(size_t)D_*D_,
                                           out, nullptr, nullptr);
}

// round 5
// speedup vs baseline: 5.8229x; 1.5386x over previous
#include <cuda_runtime.h>
#include <cuda_bf16.h>
#include <cstdint>
#include <math.h>

// ---------------- problem shape ----------------------------------------------
#define B_   2
#define S_   2048
#define D_   1024
#define H_   16
#define HD   64
#define MTOT (B_*S_)          // 4096
#define SCALE 0.125f          // 1/sqrt(64), exact power of two

// ---------------- baseline-PTX helpers (compile at compute_103) --------------
__device__ __forceinline__ uint32_t smem_u32(const void* p) {
    uint32_t a;
    asm("{ .reg .u64 t; cvta.to.shared.u64 t, %1; cvt.u32.u64 %0, t; }"
        : "=r"(a) : "l"(p));
    return a;
}
#define CP_ASYNC16(dst, src) \
    asm volatile("cp.async.cg.shared.global [%0], [%1], 16;" :: "r"(dst), "l"(src))
#define CP_COMMIT() asm volatile("cp.async.commit_group;" ::: "memory")
#define CP_WAIT2()  asm volatile("cp.async.wait_group 2;" ::: "memory")
#define CP_WAIT1()  asm volatile("cp.async.wait_group 1;" ::: "memory")
#define CP_WAIT0()  asm volatile("cp.async.wait_group 0;" ::: "memory")

__device__ __forceinline__ void ldsm4(uint32_t& r0, uint32_t& r1,
                                      uint32_t& r2, uint32_t& r3, uint32_t a) {
    asm volatile("ldmatrix.sync.aligned.m8n8.x4.shared.b16 {%0,%1,%2,%3}, [%4];"
                 : "=r"(r0), "=r"(r1), "=r"(r2), "=r"(r3) : "r"(a));
}
__device__ __forceinline__ void ldsm4t(uint32_t& r0, uint32_t& r1,
                                       uint32_t& r2, uint32_t& r3, uint32_t a) {
    asm volatile("ldmatrix.sync.aligned.m8n8.x4.trans.shared.b16 {%0,%1,%2,%3}, [%4];"
                 : "=r"(r0), "=r"(r1), "=r"(r2), "=r"(r3) : "r"(a));
}
__device__ __forceinline__ void mma_bf16(float* c,
    uint32_t a0, uint32_t a1, uint32_t a2, uint32_t a3, uint32_t b0, uint32_t b1) {
    asm volatile("mma.sync.aligned.m16n8k16.row.col.f32.bf16.bf16.f32 "
                 "{%0,%1,%2,%3}, {%4,%5,%6,%7}, {%8,%9}, {%0,%1,%2,%3};"
                 : "+f"(c[0]), "+f"(c[1]), "+f"(c[2]), "+f"(c[3])
                 : "r"(a0), "r"(a1), "r"(a2), "r"(a3), "r"(b0), "r"(b1));
}
__device__ __forceinline__ uint32_t pack_bf2(float lo, float hi) {
    __nv_bfloat162 t = __floats2bfloat162_rn(lo, hi);
    return *(uint32_t*)&t;
}

// ---------------- scratch (device globals; no allocations allowed) ----------
__device__ __nv_bfloat16 g_qh[(size_t)B_*H_*S_*HD], g_ql[(size_t)B_*H_*S_*HD];
__device__ __nv_bfloat16 g_kh[(size_t)B_*H_*S_*HD], g_kl[(size_t)B_*H_*S_*HD];
__device__ __nv_bfloat16 g_vh[(size_t)B_*H_*S_*HD], g_vl[(size_t)B_*H_*S_*HD];
__device__ __nv_bfloat16 g_xh[(size_t)MTOT*D_],  g_xl[(size_t)MTOT*D_];
__device__ __nv_bfloat16 g_wh[(size_t)4*D_*D_],  g_wl[(size_t)4*D_*D_];
__device__ __nv_bfloat16 g_ath[(size_t)MTOT*D_], g_atl[(size_t)MTOT*D_];
__device__ float2 g_rope[(size_t)S_*32];          // (cos,sin) per (spos, d/2)

// ---------------- RoPE table (exact sincosf, one-time) -----------------------
__global__ void rope_kernel(float2* __restrict__ t)
{
    int i = blockIdx.x * blockDim.x + threadIdx.x;    // over S_*32
    if (i >= S_ * 32) return;
    int spos = i >> 5, d2 = i & 31;
    float theta = powf(10000.0f, -2.0f * (float)d2 / (float)HD);
    float ang = (float)spos * theta;
    float ss, cc;
    sincosf(ang, &ss, &cc);
    t[i] = make_float2(cc, ss);
}

// ---------------- fused fp32 -> (bf16 hi, bf16 lo) split for x + 4 W ---------
#define RW  ((D_*D_)/4)        // 262144 float4 per weight
__global__ void split_all(const float* __restrict__ x,
                          const float* __restrict__ w0, const float* __restrict__ w1,
                          const float* __restrict__ w2, const float* __restrict__ w3,
                          __nv_bfloat16* __restrict__ xh, __nv_bfloat16* __restrict__ xl,
                          __nv_bfloat16* __restrict__ wh, __nv_bfloat16* __restrict__ wl)
{
    int i = blockIdx.x * blockDim.x + threadIdx.x;    // float4 index, 8*RW total
    const float* src;
    __nv_bfloat16 *hi, *lo;
    int local;
    if (i < 4 * RW) {          // x region (MTOT*D_ floats = 4*RW float4)
        src = x; hi = xh; lo = xl; local = i;
    } else {
        int ip = i - 4 * RW;
        int r  = ip >> 18;     // RW = 2^18
        local  = ip & (RW - 1);
        src = (r == 0) ? w0 : (r == 1) ? w1 : (r == 2) ? w2 : w3;
        hi = wh + (size_t)r * D_ * D_;
        lo = wl + (size_t)r * D_ * D_;
    }
    float4 v = ((const float4*)src)[local];
    __nv_bfloat16 h0 = __float2bfloat16(v.x);
    __nv_bfloat16 h1 = __float2bfloat16(v.y);
    __nv_bfloat16 h2 = __float2bfloat16(v.z);
    __nv_bfloat16 h3 = __float2bfloat16(v.w);
    __nv_bfloat16 l0 = __float2bfloat16(v.x - __bfloat162float(h0));
    __nv_bfloat16 l1 = __float2bfloat16(v.y - __bfloat162float(h1));
    __nv_bfloat16 l2 = __float2bfloat16(v.z - __bfloat162float(h2));
    __nv_bfloat16 l3 = __float2bfloat16(v.w - __bfloat162float(h3));
    __nv_bfloat162 a, b;
    a.x = h0; a.y = h1; b.x = h2; b.y = h3;
    ((__nv_bfloat162*)hi)[2*local]   = a;
    ((__nv_bfloat162*)hi)[2*local+1] = b;
    a.x = l0; a.y = l1; b.x = l2; b.y = l3;
    ((__nv_bfloat162*)lo)[2*local]   = a;
    ((__nv_bfloat162*)lo)[2*local+1] = b;
}

// ---------------- HMMA GEMM (3-stage): C[m,n] = sum_k A[m,k]*W[n,k] ----------
#define BKG 32
#define NKI (D_/BKG)       // 32
#define STG 32768          // bytes per stage
#define GSMEM (3*STG)      // 96 KB

__device__ __forceinline__ uint32_t sw_off(int row, int kc) {
    return (uint32_t)((row << 6) + ((kc ^ ((row >> 1) & 3)) << 4));
}

__device__ __forceinline__ void stage_load(
    uint32_t sb, int s, int k0, int tid, int m0, int n0,
    const __nv_bfloat16* __restrict__ Ah, const __nv_bfloat16* __restrict__ Al,
    const __nv_bfloat16* __restrict__ Bh, const __nv_bfloat16* __restrict__ Bl)
{
    const uint32_t base = sb + (uint32_t)s * STG;
#pragma unroll
    for (int p = 0; p < 2; p++) {
        const int gi  = tid + p * 256;
        const int row = gi >> 2;
        const int kc  = gi & 3;
        const uint32_t so = sw_off(row, kc);
        const size_t aoff = (size_t)(m0 + row) * D_ + k0 + kc * 8;
        const size_t boff = (size_t)(n0 + row) * D_ + k0 + kc * 8;
        CP_ASYNC16(base + 0     + so, Ah + aoff);
        CP_ASYNC16(base + 8192  + so, Al + aoff);
        CP_ASYNC16(base + 16384 + so, Bh + boff);
        CP_ASYNC16(base + 24576 + so, Bl + boff);
    }
}

// QKV=1: n0 in [0,3072), B = concatenated Wq|Wk|Wv rows; epilogue RoPE/scale +
//        bf16 hi/lo scatter to q/k/v [B,H,S,hd].
// QKV=0: n0 in [0,1024), B = Wo rows; fp32 [M,D] output.
template<int QKV>
__global__ __launch_bounds__(256, 1)
void gemm_mma(const __nv_bfloat16* __restrict__ Ah, const __nv_bfloat16* __restrict__ Al,
              const __nv_bfloat16* __restrict__ Bh, const __nv_bfloat16* __restrict__ Bl,
              float* __restrict__ Cf,
              __nv_bfloat16* __restrict__ Qh, __nv_bfloat16* __restrict__ Ql,
              __nv_bfloat16* __restrict__ Kh, __nv_bfloat16* __restrict__ Kl,
              __nv_bfloat16* __restrict__ Vh, __nv_bfloat16* __restrict__ Vl)
{
    extern __shared__ char smem[];
    const uint32_t sb = smem_u32(smem);
    const int tid  = threadIdx.x;
    const int wid  = tid >> 5;
    const int lane = tid & 31;
    const int m0 = blockIdx.y * 128;
    const int n0 = blockIdx.x * 128;
    const int wm = (wid & 1) * 64;
    const int wn = (wid >> 1) * 32;

    float acc[4][4][4];
#pragma unroll
    for (int a = 0; a < 4; a++)
#pragma unroll
        for (int b = 0; b < 4; b++)
#pragma unroll
            for (int c = 0; c < 4; c++) acc[a][b][c] = 0.f;

    stage_load(sb, 0, 0, tid, m0, n0, Ah, Al, Bh, Bl);
    CP_COMMIT();
    stage_load(sb, 1, BKG, tid, m0, n0, Ah, Al, Bh, Bl);
    CP_COMMIT();

    const int g = lane >> 3;
    const int r = lane & 7;

    for (int i = 0; i < NKI; i++) {
        if (i + 2 < NKI) {
            int s = i + 2; while (s >= 3) s -= 3;
            stage_load(sb, s, (i + 2) * BKG, tid, m0, n0, Ah, Al, Bh, Bl);
            CP_COMMIT();
            CP_WAIT2();
        } else if (i + 1 < NKI) {
            CP_WAIT1();
        } else {
            CP_WAIT0();
        }
        __syncthreads();
        int cs = i; while (cs >= 3) cs -= 3;
        const uint32_t base = sb + (uint32_t)cs * STG;
#pragma unroll
        for (int h = 0; h < 2; h++) {
            uint32_t ah[4][4], al[4][4], bhf[2][4], blf[2][4];
#pragma unroll
            for (int mi = 0; mi < 4; mi++) {
                const int arow = wm + mi * 16 + (g & 1) * 8 + r;
                const int akc  = h * 2 + (g >> 1);
                const uint32_t so = sw_off(arow, akc);
                ldsm4(ah[mi][0], ah[mi][1], ah[mi][2], ah[mi][3], base + 0 + so);
                ldsm4(al[mi][0], al[mi][1], al[mi][2], al[mi][3], base + 8192 + so);
            }
#pragma unroll
            for (int ng = 0; ng < 2; ng++) {
                const int brow = wn + ng * 16 + (g >> 1) * 8 + r;
                const int bkc  = h * 2 + (g & 1);
                const uint32_t so = sw_off(brow, bkc);
                ldsm4(bhf[ng][0], bhf[ng][1], bhf[ng][2], bhf[ng][3], base + 16384 + so);
                ldsm4(blf[ng][0], blf[ng][1], blf[ng][2], blf[ng][3], base + 24576 + so);
            }
#pragma unroll
            for (int mi = 0; mi < 4; mi++)
#pragma unroll
                for (int ni = 0; ni < 4; ni++) {
                    const uint32_t* bh = &bhf[ni >> 1][(ni & 1) * 2];
                    const uint32_t* bl = &blf[ni >> 1][(ni & 1) * 2];
                    mma_bf16(acc[mi][ni], ah[mi][0], ah[mi][1], ah[mi][2], ah[mi][3], bh[0], bh[1]);
                    mma_bf16(acc[mi][ni], ah[mi][0], ah[mi][1], ah[mi][2], ah[mi][3], bl[0], bl[1]);
                    mma_bf16(acc[mi][ni], al[mi][0], al[mi][1], al[mi][2], al[mi][3], bh[0], bh[1]);
                }
        }
        __syncthreads();
    }

    // ---------------- epilogue ------------------------------------------------
    const int w = QKV ? (n0 >> 10) : 3;       // which weight plane
    const int tg = lane >> 2;
    const int tq = lane & 3;
#pragma unroll
    for (int mi = 0; mi < 4; mi++) {
#pragma unroll
        for (int hf = 0; hf < 2; hf++) {
            const int m    = m0 + wm + mi * 16 + hf * 8 + tg;
            const int spos = m & (S_ - 1);
            const int bb   = m >> 11;
#pragma unroll
            for (int ni = 0; ni < 4; ni++) {
                const int n = n0 + wn + ni * 8 + tq * 2;     // even (global)
                float v1 = acc[mi][ni][hf * 2 + 0];
                float v2 = acc[mi][ni][hf * 2 + 1];
                if (QKV) {
                    const int nl = n & 1023;                 // within plane
                    const int d  = nl & (HD - 1);
                    if (w < 2) {
                        float2 cs = g_rope[spos * 32 + (d >> 1)];
                        float y1 = v1 * cs.x - v2 * cs.y;
                        float y2 = v1 * cs.y + v2 * cs.x;
                        v1 = y1; v2 = y2;
                    }
                    if (w == 0) { v1 *= SCALE; v2 *= SCALE; }
                    const int hh = nl >> 6;
                    const size_t idx = (((size_t)(bb * H_ + hh) * S_) + spos) * HD + d;
                    __nv_bfloat16 h1 = __float2bfloat16(v1);
                    __nv_bfloat16 h2 = __float2bfloat16(v2);
                    __nv_bfloat16 l1 = __float2bfloat16(v1 - __bfloat162float(h1));
                    __nv_bfloat16 l2 = __float2bfloat16(v2 - __bfloat162float(h2));
                    __nv_bfloat162 hp; hp.x = h1; hp.y = h2;
                    __nv_bfloat162 lp; lp.x = l1; lp.y = l2;
                    __nv_bfloat16* Ch = (w == 0) ? Qh : (w == 1) ? Kh : Vh;
                    __nv_bfloat16* Cl = (w == 0) ? Ql : (w == 1) ? Kl : Vl;
                    *(__nv_bfloat162*)(Ch + idx) = hp;
                    *(__nv_bfloat162*)(Cl + idx) = lp;
                } else {
                    float* p = Cf + (size_t)m * D_ + n;
                    *(float2*)p = make_float2(v1, v2);
                }
            }
        }
    }
}

// ---------------- HMMA flash attention (causal) ------------------------------
// 256 threads (8 warps), Q tile 128 rows (16/warp), K/V tiles 64 rows,
// double-buffered cp.async. Compensated bf16 hi/lo on QK and PV.
// smem: QH[16K] QL[16K] | 2 stages x (KH KL VH VL, 8K each) = 96KB.
#define FQ_OFF  0u
#define FQL_OFF 16384u
#define FST_OFF 32768u
#define FSTG    32768u
#define FSMEM   (32768 + 2*32768)

__device__ __forceinline__ uint32_t fsw(int row, int c) {   // 128B rows
    return (uint32_t)(row * 128 + ((c ^ (row & 7)) << 4));
}

__device__ __forceinline__ void fa_stage(
    uint32_t base, const __nv_bfloat16* kh, const __nv_bfloat16* kl,
    const __nv_bfloat16* vh, const __nv_bfloat16* vl, int s0, int tid)
{
#pragma unroll
    for (int p = 0; p < 2; p++) {
        const int gi  = tid + p * 256;       // 0..511
        const int row = gi >> 3;
        const int c   = gi & 7;
        const uint32_t off = fsw(row, c);
        const size_t g = (size_t)(s0 + row) * HD + c * 8;
        CP_ASYNC16(base + 0u     + off, kh + g);
        CP_ASYNC16(base + 8192u  + off, kl + g);
        CP_ASYNC16(base + 16384u + off, vh + g);
        CP_ASYNC16(base + 24576u + off, vl + g);
    }
}

__global__ __launch_bounds__(256, 1)
void flash_mma(const __nv_bfloat16* __restrict__ Qh, const __nv_bfloat16* __restrict__ Ql,
               const __nv_bfloat16* __restrict__ Kh, const __nv_bfloat16* __restrict__ Kl,
               const __nv_bfloat16* __restrict__ Vh, const __nv_bfloat16* __restrict__ Vl,
               __nv_bfloat16* __restrict__ Oh, __nv_bfloat16* __restrict__ Ol)
{
    extern __shared__ char smem[];
    const uint32_t sb = smem_u32(smem);
    const int tid  = threadIdx.x;
    const int wid  = tid >> 5;
    const int lane = tid & 31;
    const int bh = blockIdx.y;
    const int mt = (int)gridDim.x - 1 - (int)blockIdx.x;   // big tiles first
    const int nkt = 2 * mt + 2;                            // 64-row K tiles

    const __nv_bfloat16* qhb = Qh + ((size_t)bh * S_) * HD;
    const __nv_bfloat16* qlb = Ql + ((size_t)bh * S_) * HD;
    const __nv_bfloat16* khb_ = Kh + ((size_t)bh * S_) * HD;
    const __nv_bfloat16* klb_ = Kl + ((size_t)bh * S_) * HD;
    const __nv_bfloat16* vhb_ = Vh + ((size_t)bh * S_) * HD;
    const __nv_bfloat16* vlb_ = Vl + ((size_t)bh * S_) * HD;

    // Q tile (128 rows) + stage 0 (group 0)
#pragma unroll
    for (int p = 0; p < 4; p++) {
        const int gi  = tid + p * 256;       // 0..1023
        const int row = gi >> 3;
        const int c   = gi & 7;
        const uint32_t off = fsw(row, c);
        const size_t g = (size_t)(mt * 128 + row) * HD + c * 8;
        CP_ASYNC16(sb + FQ_OFF  + off, qhb + g);
        CP_ASYNC16(sb + FQL_OFF + off, qlb + g);
    }
    fa_stage(sb + FST_OFF, khb_, klb_, vhb_, vlb_, 0, tid);
    CP_COMMIT();

    uint32_t qhf[4][4], qlf[4][4];
    float o[8][4];
#pragma unroll
    for (int a = 0; a < 8; a++)
#pragma unroll
        for (int b = 0; b < 4; b++) o[a][b] = 0.f;
    float m0r = -1e30f, m1r = -1e30f, l0r = 0.f, l1r = 0.f;

    const int grp = lane >> 3;
    const int rr  = lane & 7;

    for (int kt = 0; kt < nkt; kt++) {
        if (kt + 1 < nkt) {
            fa_stage(sb + FST_OFF + (uint32_t)((kt + 1) & 1) * FSTG,
                     khb_, klb_, vhb_, vlb_, (kt + 1) * 64, tid);
            CP_COMMIT();
            CP_WAIT1();
        } else {
            CP_WAIT0();
        }
        __syncthreads();

        if (kt == 0) {
#pragma unroll
            for (int kc = 0; kc < 4; kc++) {
                const int row = wid * 16 + (grp & 1) * 8 + rr;
                const int c   = kc * 2 + (grp >> 1);
                const uint32_t off = fsw(row, c);
                ldsm4(qhf[kc][0], qhf[kc][1], qhf[kc][2], qhf[kc][3], sb + FQ_OFF + off);
                ldsm4(qlf[kc][0], qlf[kc][1], qlf[kc][2], qlf[kc][3], sb + FQL_OFF + off);
            }
        }

        const uint32_t st = sb + FST_OFF + (uint32_t)(kt & 1) * FSTG;

        // ---- scores S = Q K^T --------------------------------------------
        float c[8][4];
#pragma unroll
        for (int a = 0; a < 8; a++)
#pragma unroll
            for (int b = 0; b < 4; b++) c[a][b] = 0.f;

#pragma unroll
        for (int nt = 0; nt < 8; nt++) {
            const int j = nt * 8 + rr;
            uint32_t kb0[4], kb1[4], lb0[4], lb1[4];
            ldsm4(kb0[0], kb0[1], kb0[2], kb0[3], st + 0u    + fsw(j, 0 + grp));
            ldsm4(kb1[0], kb1[1], kb1[2], kb1[3], st + 0u    + fsw(j, 4 + grp));
            ldsm4(lb0[0], lb0[1], lb0[2], lb0[3], st + 8192u + fsw(j, 0 + grp));
            ldsm4(lb1[0], lb1[1], lb1[2], lb1[3], st + 8192u + fsw(j, 4 + grp));
            mma_bf16(c[nt], qhf[0][0], qhf[0][1], qhf[0][2], qhf[0][3], kb0[0], kb0[1]);
            mma_bf16(c[nt], qhf[0][0], qhf[0][1], qhf[0][2], qhf[0][3], lb0[0], lb0[1]);
            mma_bf16(c[nt], qlf[0][0], qlf[0][1], qlf[0][2], qlf[0][3], kb0[0], kb0[1]);
            mma_bf16(c[nt], qhf[1][0], qhf[1][1], qhf[1][2], qhf[1][3], kb0[2], kb0[3]);
            mma_bf16(c[nt], qhf[1][0], qhf[1][1], qhf[1][2], qhf[1][3], lb0[2], lb0[3]);
            mma_bf16(c[nt], qlf[1][0], qlf[1][1], qlf[1][2], qlf[1][3], kb0[2], kb0[3]);
            mma_bf16(c[nt], qhf[2][0], qhf[2][1], qhf[2][2], qhf[2][3], kb1[0], kb1[1]);
            mma_bf16(c[nt], qhf[2][0], qhf[2][1], qhf[2][2], qhf[2][3], lb1[0], lb1[1]);
            mma_bf16(c[nt], qlf[2][0], qlf[2][1], qlf[2][2], qlf[2][3], kb1[0], kb1[1]);
            mma_bf16(c[nt], qhf[3][0], qhf[3][1], qhf[3][2], qhf[3][3], kb1[2], kb1[3]);
            mma_bf16(c[nt], qhf[3][0], qhf[3][1], qhf[3][2], qhf[3][3], lb1[2], lb1[3]);
            mma_bf16(c[nt], qlf[3][0], qlf[3][1], qlf[3][2], qlf[3][3], kb1[2], kb1[3]);
        }

        // ---- causal mask (tiles overlapping the diagonal) ----------------
        if (kt >= 2 * mt) {
            const int joff = (kt - 2 * mt) * 64;
            const int i0 = wid * 16 + (lane >> 2);
#pragma unroll
            for (int nt = 0; nt < 8; nt++) {
                const int j0 = nt * 8 + (lane & 3) * 2 + joff;
                if (j0     > i0)     c[nt][0] = -1e30f;
                if (j0 + 1 > i0)     c[nt][1] = -1e30f;
                if (j0     > i0 + 8) c[nt][2] = -1e30f;
                if (j0 + 1 > i0 + 8) c[nt][3] = -1e30f;
            }
        }

        // ---- online softmax ----------------------------------------------
        float t0 = -1e30f, t1 = -1e30f;
#pragma unroll
        for (int nt = 0; nt < 8; nt++) {
            t0 = fmaxf(t0, fmaxf(c[nt][0], c[nt][1]));
            t1 = fmaxf(t1, fmaxf(c[nt][2], c[nt][3]));
        }
        t0 = fmaxf(t0, __shfl_xor_sync(0xffffffffu, t0, 1));
        t0 = fmaxf(t0, __shfl_xor_sync(0xffffffffu, t0, 2));
        t1 = fmaxf(t1, __shfl_xor_sync(0xffffffffu, t1, 1));
        t1 = fmaxf(t1, __shfl_xor_sync(0xffffffffu, t1, 2));
        const float mn0 = fmaxf(m0r, t0);
        const float mn1 = fmaxf(m1r, t1);
        const float al0 = __expf(m0r - mn0);
        const float al1 = __expf(m1r - mn1);
        m0r = mn0; m1r = mn1;

        float s0 = 0.f, s1 = 0.f;
#pragma unroll
        for (int nt = 0; nt < 8; nt++) {
            c[nt][0] = __expf(c[nt][0] - mn0);
            c[nt][1] = __expf(c[nt][1] - mn0);
            c[nt][2] = __expf(c[nt][2] - mn1);
            c[nt][3] = __expf(c[nt][3] - mn1);
            s0 += c[nt][0] + c[nt][1];
            s1 += c[nt][2] + c[nt][3];
        }
        s0 += __shfl_xor_sync(0xffffffffu, s0, 1);
        s0 += __shfl_xor_sync(0xffffffffu, s0, 2);
        s1 += __shfl_xor_sync(0xffffffffu, s1, 1);
        s1 += __shfl_xor_sync(0xffffffffu, s1, 2);
        l0r = l0r * al0 + s0;
        l1r = l1r * al1 + s1;

#pragma unroll
        for (int nt = 0; nt < 8; nt++) {
            o[nt][0] *= al0; o[nt][1] *= al0;
            o[nt][2] *= al1; o[nt][3] *= al1;
        }

        // ---- O += P V, P converted per-kc (low register pressure) --------
#pragma unroll
        for (int kc = 0; kc < 4; kc++) {
            uint32_t ph[4], pl[4];
            const float* p0 = c[2*kc];
            const float* p1 = c[2*kc+1];
            ph[0] = pack_bf2(p0[0], p0[1]);
            ph[1] = pack_bf2(p0[2], p0[3]);
            ph[2] = pack_bf2(p1[0], p1[1]);
            ph[3] = pack_bf2(p1[2], p1[3]);
            __nv_bfloat162 hh;
            *(uint32_t*)&hh = ph[0];
            pl[0] = pack_bf2(p0[0]-__bfloat162float(hh.x), p0[1]-__bfloat162float(hh.y));
            *(uint32_t*)&hh = ph[1];
            pl[1] = pack_bf2(p0[2]-__bfloat162float(hh.x), p0[3]-__bfloat162float(hh.y));
            *(uint32_t*)&hh = ph[2];
            pl[2] = pack_bf2(p1[0]-__bfloat162float(hh.x), p1[1]-__bfloat162float(hh.y));
            *(uint32_t*)&hh = ph[3];
            pl[3] = pack_bf2(p1[2]-__bfloat162float(hh.x), p1[3]-__bfloat162float(hh.y));
#pragma unroll
            for (int ntp = 0; ntp < 4; ntp++) {
                const int row = kc * 16 + (grp & 1) * 8 + rr;
                const int ch  = ntp * 2 + (grp >> 1);
                const uint32_t off = fsw(row, ch);
                uint32_t vh0, vh1, vh2, vh3, vl0, vl1, vl2, vl3;
                ldsm4t(vh0, vh1, vh2, vh3, st + 16384u + off);
                ldsm4t(vl0, vl1, vl2, vl3, st + 24576u + off);
                mma_bf16(o[2*ntp],   ph[0], ph[1], ph[2], ph[3], vh0, vh1);
                mma_bf16(o[2*ntp],   ph[0], ph[1], ph[2], ph[3], vl0, vl1);
                mma_bf16(o[2*ntp],   pl[0], pl[1], pl[2], pl[3], vh0, vh1);
                mma_bf16(o[2*ntp+1], ph[0], ph[1], ph[2], ph[3], vh2, vh3);
                mma_bf16(o[2*ntp+1], ph[0], ph[1], ph[2], ph[3], vl2, vl3);
                mma_bf16(o[2*ntp+1], pl[0], pl[1], pl[2], pl[3], vh2, vh3);
            }
        }
        __syncthreads();
    }

    // ---- finalize + write bf16 hi/lo [B,S,D] --------------------------------
    const float inv0 = 1.f / l0r;
    const float inv1 = 1.f / l1r;
    const int b = bh >> 4;
    const int h = bh & (H_ - 1);
    const int sq0 = mt * 128 + wid * 16 + (lane >> 2);
    const size_t base0 = ((size_t)(b * S_ + sq0)) * D_ + h * HD;
    const size_t base1 = base0 + (size_t)8 * D_;
#pragma unroll
    for (int nt = 0; nt < 8; nt++) {
        const int col = nt * 8 + (lane & 3) * 2;
        {
            float v0 = o[nt][0] * inv0, v1 = o[nt][1] * inv0;
            __nv_bfloat16 h0 = __float2bfloat16(v0);
            __nv_bfloat16 h1 = __float2bfloat16(v1);
            __nv_bfloat16 l0 = __float2bfloat16(v0 - __bfloat162float(h0));
            __nv_bfloat16 l1 = __float2bfloat16(v1 - __bfloat162float(h1));
            __nv_bfloat162 hp; hp.x = h0; hp.y = h1;
            __nv_bfloat162 lp; lp.x = l0; lp.y = l1;
            *(__nv_bfloat162*)(Oh + base0 + col) = hp;
            *(__nv_bfloat162*)(Ol + base0 + col) = lp;
        }
        {
            float v0 = o[nt][2] * inv1, v1 = o[nt][3] * inv1;
            __nv_bfloat16 h0 = __float2bfloat16(v0);
            __nv_bfloat16 h1 = __float2bfloat16(v1);
            __nv_bfloat16 l0 = __float2bfloat16(v0 - __bfloat162float(h0));
            __nv_bfloat16 l1 = __float2bfloat16(v1 - __bfloat162float(h1));
            __nv_bfloat162 hp; hp.x = h0; hp.y = h1;
            __nv_bfloat162 lp; lp.x = l0; lp.y = l1;
            *(__nv_bfloat162*)(Oh + base1 + col) = hp;
            *(__nv_bfloat162*)(Ol + base1 + col) = lp;
        }
    }
}

// ---------------- launch -----------------------------------------------------
extern "C" void kernel_launch(void* const* d_in, const int* in_sizes, int n_in,
                              void* d_out, int out_size)
{
    const float* x  = (const float*)d_in[0];
    float* out = (float*)d_out;

    void *pqh, *pql, *pkh, *pkl, *pvh, *pvl, *pxh, *pxl, *pwh, *pwl, *path, *patl, *prope;
    cudaGetSymbolAddress(&pqh, g_qh);  cudaGetSymbolAddress(&pql, g_ql);
    cudaGetSymbolAddress(&pkh, g_kh);  cudaGetSymbolAddress(&pkl, g_kl);
    cudaGetSymbolAddress(&pvh, g_vh);  cudaGetSymbolAddress(&pvl, g_vl);
    cudaGetSymbolAddress(&pxh, g_xh);  cudaGetSymbolAddress(&pxl, g_xl);
    cudaGetSymbolAddress(&pwh, g_wh);  cudaGetSymbolAddress(&pwl, g_wl);
    cudaGetSymbolAddress(&path, g_ath); cudaGetSymbolAddress(&patl, g_atl);
    cudaGetSymbolAddress(&prope, g_rope);

    cudaFuncSetAttribute(gemm_mma<1>, cudaFuncAttributeMaxDynamicSharedMemorySize, GSMEM);
    cudaFuncSetAttribute(gemm_mma<0>, cudaFuncAttributeMaxDynamicSharedMemorySize, GSMEM);
    cudaFuncSetAttribute(flash_mma, cudaFuncAttributeMaxDynamicSharedMemorySize, FSMEM);

    __nv_bfloat16* xh = (__nv_bfloat16*)pxh;
    __nv_bfloat16* xl = (__nv_bfloat16*)pxl;
    __nv_bfloat16* wh = (__nv_bfloat16*)pwh;
    __nv_bfloat16* wl = (__nv_bfloat16*)pwl;

    // RoPE table + fused splits
    rope_kernel<<<(S_ * 32 + 255) / 256, 256>>>((float2*)prope);
    split_all<<<(8 * RW) / 256, 256>>>(x, (const float*)d_in[1], (const float*)d_in[2],
                                       (const float*)d_in[3], (const float*)d_in[4],
                                       xh, xl, wh, wl);

    // fused QKV projection (RoPE/scale in epilogue) -> bf16 hi/lo [B,H,S,hd]
    dim3 qkvgrid(3 * D_ / 128, MTOT / 128);   // (24, 32)
    gemm_mma<1><<<qkvgrid, 256, GSMEM>>>(xh, xl, wh, wl, nullptr,
        (__nv_bfloat16*)pqh, (__nv_bfloat16*)pql,
        (__nv_bfloat16*)pkh, (__nv_bfloat16*)pkl,
        (__nv_bfloat16*)pvh, (__nv_bfloat16*)pvl);

    // tensor-core causal flash attention -> bf16 hi/lo [B,S,D]
    dim3 agrid(S_ / 128, B_ * H_);       // (16, 32)
    flash_mma<<<agrid, 256, FSMEM>>>((const __nv_bfloat16*)pqh, (const __nv_bfloat16*)pql,
                                     (const __nv_bfloat16*)pkh, (const __nv_bfloat16*)pkl,
                                     (const __nv_bfloat16*)pvh, (const __nv_bfloat16*)pvl,
                                     (__nv_bfloat16*)path, (__nv_bfloat16*)patl);

    // output projection -> d_out (fp32)
    dim3 ogrid(D_ / 128, MTOT / 128);    // (8, 32)
    gemm_mma<0><<<ogrid, 256, GSMEM>>>((const __nv_bfloat16*)path, (const __nv_bfloat16*)patl,
                                       wh + 3*(size_t)D_*D_, wl + 3*(size_t)D_*D_,
                                       out, nullptr, nullptr, nullptr, nullptr, nullptr, nullptr);
}

// round 7
// speedup vs baseline: 6.0301x; 1.0356x over previous
#include <cuda_runtime.h>
#include <cuda_bf16.h>
#include <cstdint>
#include <math.h>

// ---------------- problem shape ----------------------------------------------
#define B_   2
#define S_   2048
#define D_   1024
#define H_   16
#define HD   64
#define MTOT (B_*S_)          // 4096
#define SCALE 0.125f          // 1/sqrt(64), exact power of two

// ---------------- baseline-PTX helpers (compile at compute_103) --------------
__device__ __forceinline__ uint32_t smem_u32(const void* p) {
    uint32_t a;
    asm("{ .reg .u64 t; cvta.to.shared.u64 t, %1; cvt.u32.u64 %0, t; }"
        : "=r"(a) : "l"(p));
    return a;
}
#define CP_ASYNC16(dst, src) \
    asm volatile("cp.async.cg.shared.global [%0], [%1], 16;" :: "r"(dst), "l"(src))
#define CP_COMMIT() asm volatile("cp.async.commit_group;" ::: "memory")
#define CP_WAIT2()  asm volatile("cp.async.wait_group 2;" ::: "memory")
#define CP_WAIT1()  asm volatile("cp.async.wait_group 1;" ::: "memory")
#define CP_WAIT0()  asm volatile("cp.async.wait_group 0;" ::: "memory")

__device__ __forceinline__ void ldsm4(uint32_t& r0, uint32_t& r1,
                                      uint32_t& r2, uint32_t& r3, uint32_t a) {
    asm volatile("ldmatrix.sync.aligned.m8n8.x4.shared.b16 {%0,%1,%2,%3}, [%4];"
                 : "=r"(r0), "=r"(r1), "=r"(r2), "=r"(r3) : "r"(a));
}
__device__ __forceinline__ void ldsm4t(uint32_t& r0, uint32_t& r1,
                                       uint32_t& r2, uint32_t& r3, uint32_t a) {
    asm volatile("ldmatrix.sync.aligned.m8n8.x4.trans.shared.b16 {%0,%1,%2,%3}, [%4];"
                 : "=r"(r0), "=r"(r1), "=r"(r2), "=r"(r3) : "r"(a));
}
__device__ __forceinline__ void mma_bf16(float* c,
    uint32_t a0, uint32_t a1, uint32_t a2, uint32_t a3, uint32_t b0, uint32_t b1) {
    asm volatile("mma.sync.aligned.m16n8k16.row.col.f32.bf16.bf16.f32 "
                 "{%0,%1,%2,%3}, {%4,%5,%6,%7}, {%8,%9}, {%0,%1,%2,%3};"
                 : "+f"(c[0]), "+f"(c[1]), "+f"(c[2]), "+f"(c[3])
                 : "r"(a0), "r"(a1), "r"(a2), "r"(a3), "r"(b0), "r"(b1));
}
__device__ __forceinline__ uint32_t pack_bf2(float lo, float hi) {
    __nv_bfloat162 t = __floats2bfloat162_rn(lo, hi);
    return *(uint32_t*)&t;
}

// ---------------- scratch (device globals; no allocations allowed) ----------
__device__ __nv_bfloat16 g_qh[(size_t)B_*H_*S_*HD], g_ql[(size_t)B_*H_*S_*HD];
__device__ __nv_bfloat16 g_kh[(size_t)B_*H_*S_*HD], g_kl[(size_t)B_*H_*S_*HD];
__device__ __nv_bfloat16 g_vh[(size_t)B_*H_*S_*HD], g_vl[(size_t)B_*H_*S_*HD];
__device__ __nv_bfloat16 g_xh[(size_t)MTOT*D_],  g_xl[(size_t)MTOT*D_];
__device__ __nv_bfloat16 g_wh[(size_t)4*D_*D_],  g_wl[(size_t)4*D_*D_];
__device__ __nv_bfloat16 g_ath[(size_t)MTOT*D_], g_atl[(size_t)MTOT*D_];
__device__ float2 g_rope[(size_t)S_*32];          // (cos,sin) per (spos, d/2)

// ---------------- RoPE table (exact sincosf, one-time) -----------------------
__global__ void rope_kernel(float2* __restrict__ t)
{
    int i = blockIdx.x * blockDim.x + threadIdx.x;    // over S_*32
    if (i >= S_ * 32) return;
    int spos = i >> 5, d2 = i & 31;
    float theta = powf(10000.0f, -2.0f * (float)d2 / (float)HD);
    float ang = (float)spos * theta;
    float ss, cc;
    sincosf(ang, &ss, &cc);
    t[i] = make_float2(cc, ss);
}

// ---------------- fused fp32 -> (bf16 hi, bf16 lo) split for x + 4 W ---------
#define RW  ((D_*D_)/4)        // 262144 float4 per weight
__global__ void split_all(const float* __restrict__ x,
                          const float* __restrict__ w0, const float* __restrict__ w1,
                          const float* __restrict__ w2, const float* __restrict__ w3,
                          __nv_bfloat16* __restrict__ xh, __nv_bfloat16* __restrict__ xl,
                          __nv_bfloat16* __restrict__ wh, __nv_bfloat16* __restrict__ wl)
{
    int i = blockIdx.x * blockDim.x + threadIdx.x;    // float4 index, 8*RW total
    const float* src;
    __nv_bfloat16 *hi, *lo;
    int local;
    if (i < 4 * RW) {
        src = x; hi = xh; lo = xl; local = i;
    } else {
        int ip = i - 4 * RW;
        int r  = ip >> 18;     // RW = 2^18
        local  = ip & (RW - 1);
        src = (r == 0) ? w0 : (r == 1) ? w1 : (r == 2) ? w2 : w3;
        hi = wh + (size_t)r * D_ * D_;
        lo = wl + (size_t)r * D_ * D_;
    }
    float4 v = ((const float4*)src)[local];
    __nv_bfloat16 h0 = __float2bfloat16(v.x);
    __nv_bfloat16 h1 = __float2bfloat16(v.y);
    __nv_bfloat16 h2 = __float2bfloat16(v.z);
    __nv_bfloat16 h3 = __float2bfloat16(v.w);
    __nv_bfloat16 l0 = __float2bfloat16(v.x - __bfloat162float(h0));
    __nv_bfloat16 l1 = __float2bfloat16(v.y - __bfloat162float(h1));
    __nv_bfloat16 l2 = __float2bfloat16(v.z - __bfloat162float(h2));
    __nv_bfloat16 l3 = __float2bfloat16(v.w - __bfloat162float(h3));
    __nv_bfloat162 a, b;
    a.x = h0; a.y = h1; b.x = h2; b.y = h3;
    ((__nv_bfloat162*)hi)[2*i >= 0 ? 2*local : 0]   = a;
    ((__nv_bfloat162*)hi)[2*local+1] = b;
    a.x = l0; a.y = l1; b.x = l2; b.y = l3;
    ((__nv_bfloat162*)lo)[2*local]   = a;
    ((__nv_bfloat162*)lo)[2*local+1] = b;
}

// ---------------- HMMA GEMM (3-stage): C[m,n] = sum_k A[m,k]*W[n,k] ----------
#define BKG 32
#define NKI (D_/BKG)       // 32
#define STG 32768          // bytes per stage
#define GSMEM (3*STG)      // 96 KB

__device__ __forceinline__ uint32_t sw_off(int row, int kc) {
    return (uint32_t)((row << 6) + ((kc ^ ((row >> 1) & 3)) << 4));
}

__device__ __forceinline__ void stage_load(
    uint32_t sb, int s, int k0, int tid, int m0, int n0,
    const __nv_bfloat16* __restrict__ Ah, const __nv_bfloat16* __restrict__ Al,
    const __nv_bfloat16* __restrict__ Bh, const __nv_bfloat16* __restrict__ Bl)
{
    const uint32_t base = sb + (uint32_t)s * STG;
#pragma unroll
    for (int p = 0; p < 2; p++) {
        const int gi  = tid + p * 256;
        const int row = gi >> 2;
        const int kc  = gi & 3;
        const uint32_t so = sw_off(row, kc);
        const size_t aoff = (size_t)(m0 + row) * D_ + k0 + kc * 8;
        const size_t boff = (size_t)(n0 + row) * D_ + k0 + kc * 8;
        CP_ASYNC16(base + 0     + so, Ah + aoff);
        CP_ASYNC16(base + 8192  + so, Al + aoff);
        CP_ASYNC16(base + 16384 + so, Bh + boff);
        CP_ASYNC16(base + 24576 + so, Bl + boff);
    }
}

// QKV=1: n0 in [0,3072): B = Wq|Wk|Wv rows; RoPE/scale + bf16 hi/lo scatter.
// QKV=0: n0 in [0,1024): B = Wo rows; fp32 [M,D] output.
template<int QKV>
__global__ __launch_bounds__(256, 1)
void gemm_mma(const __nv_bfloat16* __restrict__ Ah, const __nv_bfloat16* __restrict__ Al,
              const __nv_bfloat16* __restrict__ Bh, const __nv_bfloat16* __restrict__ Bl,
              float* __restrict__ Cf,
              __nv_bfloat16* __restrict__ Qh, __nv_bfloat16* __restrict__ Ql,
              __nv_bfloat16* __restrict__ Kh, __nv_bfloat16* __restrict__ Kl,
              __nv_bfloat16* __restrict__ Vh, __nv_bfloat16* __restrict__ Vl)
{
    extern __shared__ char smem[];
    const uint32_t sb = smem_u32(smem);
    const int tid  = threadIdx.x;
    const int wid  = tid >> 5;
    const int lane = tid & 31;
    const int m0 = blockIdx.y * 128;
    const int n0 = blockIdx.x * 128;
    const int wm = (wid & 1) * 64;
    const int wn = (wid >> 1) * 32;

    float acc[4][4][4];
#pragma unroll
    for (int a = 0; a < 4; a++)
#pragma unroll
        for (int b = 0; b < 4; b++)
#pragma unroll
            for (int c = 0; c < 4; c++) acc[a][b][c] = 0.f;

    stage_load(sb, 0, 0, tid, m0, n0, Ah, Al, Bh, Bl);
    CP_COMMIT();
    stage_load(sb, 1, BKG, tid, m0, n0, Ah, Al, Bh, Bl);
    CP_COMMIT();

    const int g = lane >> 3;
    const int r = lane & 7;

    for (int i = 0; i < NKI; i++) {
        if (i + 2 < NKI) {
            int s = i + 2; while (s >= 3) s -= 3;
            stage_load(sb, s, (i + 2) * BKG, tid, m0, n0, Ah, Al, Bh, Bl);
            CP_COMMIT();
            CP_WAIT2();
        } else if (i + 1 < NKI) {
            CP_WAIT1();
        } else {
            CP_WAIT0();
        }
        __syncthreads();     // cross-thread visibility of stage i's cp.asyncs
        int cs = i; while (cs >= 3) cs -= 3;
        const uint32_t base = sb + (uint32_t)cs * STG;
#pragma unroll
        for (int h = 0; h < 2; h++) {
            uint32_t ah[4][4], al[4][4], bhf[2][4], blf[2][4];
#pragma unroll
            for (int mi = 0; mi < 4; mi++) {
                const int arow = wm + mi * 16 + (g & 1) * 8 + r;
                const int akc  = h * 2 + (g >> 1);
                const uint32_t so = sw_off(arow, akc);
                ldsm4(ah[mi][0], ah[mi][1], ah[mi][2], ah[mi][3], base + 0 + so);
                ldsm4(al[mi][0], al[mi][1], al[mi][2], al[mi][3], base + 8192 + so);
            }
#pragma unroll
            for (int ng = 0; ng < 2; ng++) {
                const int brow = wn + ng * 16 + (g >> 1) * 8 + r;
                const int bkc  = h * 2 + (g & 1);
                const uint32_t so = sw_off(brow, bkc);
                ldsm4(bhf[ng][0], bhf[ng][1], bhf[ng][2], bhf[ng][3], base + 16384 + so);
                ldsm4(blf[ng][0], blf[ng][1], blf[ng][2], blf[ng][3], base + 24576 + so);
            }
#pragma unroll
            for (int mi = 0; mi < 4; mi++)
#pragma unroll
                for (int ni = 0; ni < 4; ni++) {
                    const uint32_t* bh = &bhf[ni >> 1][(ni & 1) * 2];
                    const uint32_t* bl = &blf[ni >> 1][(ni & 1) * 2];
                    mma_bf16(acc[mi][ni], ah[mi][0], ah[mi][1], ah[mi][2], ah[mi][3], bh[0], bh[1]);
                    mma_bf16(acc[mi][ni], ah[mi][0], ah[mi][1], ah[mi][2], ah[mi][3], bl[0], bl[1]);
                    mma_bf16(acc[mi][ni], al[mi][0], al[mi][1], al[mi][2], al[mi][3], bh[0], bh[1]);
                }
        }
        __syncthreads();     // all reads of this stage done before it is refilled
    }

    // ---------------- epilogue ------------------------------------------------
    const int w = QKV ? (n0 >> 10) : 3;
    const int tg = lane >> 2;
    const int tq = lane & 3;
#pragma unroll
    for (int mi = 0; mi < 4; mi++) {
#pragma unroll
        for (int hf = 0; hf < 2; hf++) {
            const int m    = m0 + wm + mi * 16 + hf * 8 + tg;
            const int spos = m & (S_ - 1);
            const int bb   = m >> 11;
#pragma unroll
            for (int ni = 0; ni < 4; ni++) {
                const int n = n0 + wn + ni * 8 + tq * 2;     // even (global)
                float v1 = acc[mi][ni][hf * 2 + 0];
                float v2 = acc[mi][ni][hf * 2 + 1];
                if (QKV) {
                    const int nl = n & 1023;
                    const int d  = nl & (HD - 1);
                    if (w < 2) {
                        float2 cs = g_rope[spos * 32 + (d >> 1)];
                        float y1 = v1 * cs.x - v2 * cs.y;
                        float y2 = v1 * cs.y + v2 * cs.x;
                        v1 = y1; v2 = y2;
                    }
                    if (w == 0) { v1 *= SCALE; v2 *= SCALE; }
                    const int hh = nl >> 6;
                    const size_t idx = (((size_t)(bb * H_ + hh) * S_) + spos) * HD + d;
                    __nv_bfloat16 h1 = __float2bfloat16(v1);
                    __nv_bfloat16 h2 = __float2bfloat16(v2);
                    __nv_bfloat16 l1 = __float2bfloat16(v1 - __bfloat162float(h1));
                    __nv_bfloat16 l2 = __float2bfloat16(v2 - __bfloat162float(h2));
                    __nv_bfloat162 hp; hp.x = h1; hp.y = h2;
                    __nv_bfloat162 lp; lp.x = l1; lp.y = l2;
                    __nv_bfloat16* Ch = (w == 0) ? Qh : (w == 1) ? Kh : Vh;
                    __nv_bfloat16* Cl = (w == 0) ? Ql : (w == 1) ? Kl : Vl;
                    *(__nv_bfloat162*)(Ch + idx) = hp;
                    *(__nv_bfloat162*)(Cl + idx) = lp;
                } else {
                    float* p = Cf + (size_t)m * D_ + n;
                    *(float2*)p = make_float2(v1, v2);
                }
            }
        }
    }
}

// ---------------- HMMA flash attention (causal) ------------------------------
// 128 threads (4 warps), Q tile 64 rows (16/warp), K/V tiles 64 rows,
// double-buffered cp.async, 80KB smem, __launch_bounds__(128,2) -> 2 CTAs/SM
// so co-resident CTAs overlap softmax with MMA. Two barriers per tile:
// one after cp.async wait (cross-thread visibility), one after compute
// (protect the buffer about to be refilled).
#define FQ_OFF  0u
#define FQL_OFF 8192u
#define FST_OFF 16384u
#define FSTG    32768u
#define FSMEM   (16384 + 2*32768)

__device__ __forceinline__ uint32_t fsw(int row, int c) {   // 128B rows
    return (uint32_t)(row * 128 + ((c ^ (row & 7)) << 4));
}

__device__ __forceinline__ void fa_stage(
    uint32_t base, const __nv_bfloat16* kh, const __nv_bfloat16* kl,
    const __nv_bfloat16* vh, const __nv_bfloat16* vl, int s0, int tid)
{
#pragma unroll
    for (int p = 0; p < 4; p++) {
        const int gi  = tid + p * 128;       // 0..511
        const int row = gi >> 3;
        const int c   = gi & 7;
        const uint32_t off = fsw(row, c);
        const size_t g = (size_t)(s0 + row) * HD + c * 8;
        CP_ASYNC16(base + 0u     + off, kh + g);
        CP_ASYNC16(base + 8192u  + off, kl + g);
        CP_ASYNC16(base + 16384u + off, vh + g);
        CP_ASYNC16(base + 24576u + off, vl + g);
    }
}

__global__ __launch_bounds__(128, 2)
void flash_mma(const __nv_bfloat16* __restrict__ Qh, const __nv_bfloat16* __restrict__ Ql,
               const __nv_bfloat16* __restrict__ Kh, const __nv_bfloat16* __restrict__ Kl,
               const __nv_bfloat16* __restrict__ Vh, const __nv_bfloat16* __restrict__ Vl,
               __nv_bfloat16* __restrict__ Oh, __nv_bfloat16* __restrict__ Ol)
{
    extern __shared__ char smem[];
    const uint32_t sb = smem_u32(smem);
    const int tid  = threadIdx.x;
    const int wid  = tid >> 5;
    const int lane = tid & 31;
    const int bh = blockIdx.y;
    const int mt = (int)gridDim.x - 1 - (int)blockIdx.x;   // big tiles first
    const int nkt = mt + 1;                                // 64-row K tiles

    const __nv_bfloat16* qhb = Qh + ((size_t)bh * S_) * HD;
    const __nv_bfloat16* qlb = Ql + ((size_t)bh * S_) * HD;
    const __nv_bfloat16* khb_ = Kh + ((size_t)bh * S_) * HD;
    const __nv_bfloat16* klb_ = Kl + ((size_t)bh * S_) * HD;
    const __nv_bfloat16* vhb_ = Vh + ((size_t)bh * S_) * HD;
    const __nv_bfloat16* vlb_ = Vl + ((size_t)bh * S_) * HD;

    // Q tile (64 rows) + stage 0
#pragma unroll
    for (int p = 0; p < 4; p++) {
        const int gi  = tid + p * 128;       // 0..511
        const int row = gi >> 3;
        const int c   = gi & 7;
        const uint32_t off = fsw(row, c);
        const size_t g = (size_t)(mt * 64 + row) * HD + c * 8;
        CP_ASYNC16(sb + FQ_OFF  + off, qhb + g);
        CP_ASYNC16(sb + FQL_OFF + off, qlb + g);
    }
    fa_stage(sb + FST_OFF, khb_, klb_, vhb_, vlb_, 0, tid);
    CP_COMMIT();

    uint32_t qhf[4][4], qlf[4][4];
    float o[8][4];
#pragma unroll
    for (int a = 0; a < 8; a++)
#pragma unroll
        for (int b = 0; b < 4; b++) o[a][b] = 0.f;
    float m0r = -1e30f, m1r = -1e30f, l0r = 0.f, l1r = 0.f;

    const int grp = lane >> 3;
    const int rr  = lane & 7;

    for (int kt = 0; kt < nkt; kt++) {
        if (kt + 1 < nkt) {
            fa_stage(sb + FST_OFF + (uint32_t)((kt + 1) & 1) * FSTG,
                     khb_, klb_, vhb_, vlb_, (kt + 1) * 64, tid);
            CP_COMMIT();
            CP_WAIT1();
        } else {
            CP_WAIT0();
        }
        __syncthreads();     // stage kt visible to all threads

        if (kt == 0) {
#pragma unroll
            for (int kc = 0; kc < 4; kc++) {
                const int row = wid * 16 + (grp & 1) * 8 + rr;
                const int c   = kc * 2 + (grp >> 1);
                const uint32_t off = fsw(row, c);
                ldsm4(qhf[kc][0], qhf[kc][1], qhf[kc][2], qhf[kc][3], sb + FQ_OFF + off);
                ldsm4(qlf[kc][0], qlf[kc][1], qlf[kc][2], qlf[kc][3], sb + FQL_OFF + off);
            }
        }

        const uint32_t st = sb + FST_OFF + (uint32_t)(kt & 1) * FSTG;

        // ---- scores S = Q K^T --------------------------------------------
        float c[8][4];
#pragma unroll
        for (int a = 0; a < 8; a++)
#pragma unroll
            for (int b = 0; b < 4; b++) c[a][b] = 0.f;

#pragma unroll
        for (int nt = 0; nt < 8; nt++) {
            const int j = nt * 8 + rr;
            uint32_t kb0[4], kb1[4], lb0[4], lb1[4];
            ldsm4(kb0[0], kb0[1], kb0[2], kb0[3], st + 0u    + fsw(j, 0 + grp));
            ldsm4(kb1[0], kb1[1], kb1[2], kb1[3], st + 0u    + fsw(j, 4 + grp));
            ldsm4(lb0[0], lb0[1], lb0[2], lb0[3], st + 8192u + fsw(j, 0 + grp));
            ldsm4(lb1[0], lb1[1], lb1[2], lb1[3], st + 8192u + fsw(j, 4 + grp));
            mma_bf16(c[nt], qhf[0][0], qhf[0][1], qhf[0][2], qhf[0][3], kb0[0], kb0[1]);
            mma_bf16(c[nt], qhf[0][0], qhf[0][1], qhf[0][2], qhf[0][3], lb0[0], lb0[1]);
            mma_bf16(c[nt], qlf[0][0], qlf[0][1], qlf[0][2], qlf[0][3], kb0[0], kb0[1]);
            mma_bf16(c[nt], qhf[1][0], qhf[1][1], qhf[1][2], qhf[1][3], kb0[2], kb0[3]);
            mma_bf16(c[nt], qhf[1][0], qhf[1][1], qhf[1][2], qhf[1][3], lb0[2], lb0[3]);
            mma_bf16(c[nt], qlf[1][0], qlf[1][1], qlf[1][2], qlf[1][3], kb0[2], kb0[3]);
            mma_bf16(c[nt], qhf[2][0], qhf[2][1], qhf[2][2], qhf[2][3], kb1[0], kb1[1]);
            mma_bf16(c[nt], qhf[2][0], qhf[2][1], qhf[2][2], qhf[2][3], lb1[0], lb1[1]);
            mma_bf16(c[nt], qlf[2][0], qlf[2][1], qlf[2][2], qlf[2][3], kb1[0], kb1[1]);
            mma_bf16(c[nt], qhf[3][0], qhf[3][1], qhf[3][2], qhf[3][3], kb1[2], kb1[3]);
            mma_bf16(c[nt], qhf[3][0], qhf[3][1], qhf[3][2], qhf[3][3], lb1[2], lb1[3]);
            mma_bf16(c[nt], qlf[3][0], qlf[3][1], qlf[3][2], qlf[3][3], kb1[2], kb1[3]);
        }

        // ---- causal mask on diagonal tile --------------------------------
        if (kt == mt) {
            const int i0 = wid * 16 + (lane >> 2);
#pragma unroll
            for (int nt = 0; nt < 8; nt++) {
                const int j0 = nt * 8 + (lane & 3) * 2;
                if (j0     > i0)     c[nt][0] = -1e30f;
                if (j0 + 1 > i0)     c[nt][1] = -1e30f;
                if (j0     > i0 + 8) c[nt][2] = -1e30f;
                if (j0 + 1 > i0 + 8) c[nt][3] = -1e30f;
            }
        }

        // ---- online softmax ----------------------------------------------
        float t0 = -1e30f, t1 = -1e30f;
#pragma unroll
        for (int nt = 0; nt < 8; nt++) {
            t0 = fmaxf(t0, fmaxf(c[nt][0], c[nt][1]));
            t1 = fmaxf(t1, fmaxf(c[nt][2], c[nt][3]));
        }
        t0 = fmaxf(t0, __shfl_xor_sync(0xffffffffu, t0, 1));
        t0 = fmaxf(t0, __shfl_xor_sync(0xffffffffu, t0, 2));
        t1 = fmaxf(t1, __shfl_xor_sync(0xffffffffu, t1, 1));
        t1 = fmaxf(t1, __shfl_xor_sync(0xffffffffu, t1, 2));
        const float mn0 = fmaxf(m0r, t0);
        const float mn1 = fmaxf(m1r, t1);
        const float al0 = __expf(m0r - mn0);
        const float al1 = __expf(m1r - mn1);
        m0r = mn0; m1r = mn1;

        float s0 = 0.f, s1 = 0.f;
#pragma unroll
        for (int nt = 0; nt < 8; nt++) {
            c[nt][0] = __expf(c[nt][0] - mn0);
            c[nt][1] = __expf(c[nt][1] - mn0);
            c[nt][2] = __expf(c[nt][2] - mn1);
            c[nt][3] = __expf(c[nt][3] - mn1);
            s0 += c[nt][0] + c[nt][1];
            s1 += c[nt][2] + c[nt][3];
        }
        s0 += __shfl_xor_sync(0xffffffffu, s0, 1);
        s0 += __shfl_xor_sync(0xffffffffu, s0, 2);
        s1 += __shfl_xor_sync(0xffffffffu, s1, 1);
        s1 += __shfl_xor_sync(0xffffffffu, s1, 2);
        l0r = l0r * al0 + s0;
        l1r = l1r * al1 + s1;

#pragma unroll
        for (int nt = 0; nt < 8; nt++) {
            o[nt][0] *= al0; o[nt][1] *= al0;
            o[nt][2] *= al1; o[nt][3] *= al1;
        }

        // ---- O += P V, P converted per-kc (low register pressure) --------
#pragma unroll
        for (int kc = 0; kc < 4; kc++) {
            uint32_t ph[4], pl[4];
            const float* p0 = c[2*kc];
            const float* p1 = c[2*kc+1];
            ph[0] = pack_bf2(p0[0], p0[1]);
            ph[1] = pack_bf2(p0[2], p0[3]);
            ph[2] = pack_bf2(p1[0], p1[1]);
            ph[3] = pack_bf2(p1[2], p1[3]);
            __nv_bfloat162 hh;
            *(uint32_t*)&hh = ph[0];
            pl[0] = pack_bf2(p0[0]-__bfloat162float(hh.x), p0[1]-__bfloat162float(hh.y));
            *(uint32_t*)&hh = ph[1];
            pl[1] = pack_bf2(p0[2]-__bfloat162float(hh.x), p0[3]-__bfloat162float(hh.y));
            *(uint32_t*)&hh = ph[2];
            pl[2] = pack_bf2(p1[0]-__bfloat162float(hh.x), p1[1]-__bfloat162float(hh.y));
            *(uint32_t*)&hh = ph[3];
            pl[3] = pack_bf2(p1[2]-__bfloat162float(hh.x), p1[3]-__bfloat162float(hh.y));
#pragma unroll
            for (int ntp = 0; ntp < 4; ntp++) {
                const int row = kc * 16 + (grp & 1) * 8 + rr;
                const int ch  = ntp * 2 + (grp >> 1);
                const uint32_t off = fsw(row, ch);
                uint32_t vh0, vh1, vh2, vh3, vl0, vl1, vl2, vl3;
                ldsm4t(vh0, vh1, vh2, vh3, st + 16384u + off);
                ldsm4t(vl0, vl1, vl2, vl3, st + 24576u + off);
                mma_bf16(o[2*ntp],   ph[0], ph[1], ph[2], ph[3], vh0, vh1);
                mma_bf16(o[2*ntp],   ph[0], ph[1], ph[2], ph[3], vl0, vl1);
                mma_bf16(o[2*ntp],   pl[0], pl[1], pl[2], pl[3], vh0, vh1);
                mma_bf16(o[2*ntp+1], ph[0], ph[1], ph[2], ph[3], vh2, vh3);
                mma_bf16(o[2*ntp+1], ph[0], ph[1], ph[2], ph[3], vl2, vl3);
                mma_bf16(o[2*ntp+1], pl[0], pl[1], pl[2], pl[3], vh2, vh3);
            }
        }
        __syncthreads();     // all reads of this buffer done before refill
    }

    // ---- finalize + write bf16 hi/lo [B,S,D] --------------------------------
    const float inv0 = 1.f / l0r;
    const float inv1 = 1.f / l1r;
    const int b = bh >> 4;
    const int h = bh & (H_ - 1);
    const int sq0 = mt * 64 + wid * 16 + (lane >> 2);
    const size_t base0 = ((size_t)(b * S_ + sq0)) * D_ + h * HD;
    const size_t base1 = base0 + (size_t)8 * D_;
#pragma unroll
    for (int nt = 0; nt < 8; nt++) {
        const int col = nt * 8 + (lane & 3) * 2;
        {
            float v0 = o[nt][0] * inv0, v1 = o[nt][1] * inv0;
            __nv_bfloat16 h0 = __float2bfloat16(v0);
            __nv_bfloat16 h1 = __float2bfloat16(v1);
            __nv_bfloat16 l0 = __float2bfloat16(v0 - __bfloat162float(h0));
            __nv_bfloat16 l1 = __float2bfloat16(v1 - __bfloat162float(h1));
            __nv_bfloat162 hp; hp.x = h0; hp.y = h1;
            __nv_bfloat162 lp; lp.x = l0; lp.y = l1;
            *(__nv_bfloat162*)(Oh + base0 + col) = hp;
            *(__nv_bfloat162*)(Ol + base0 + col) = lp;
        }
        {
            float v0 = o[nt][2] * inv1, v1 = o[nt][3] * inv1;
            __nv_bfloat16 h0 = __float2bfloat16(v0);
            __nv_bfloat16 h1 = __float2bfloat16(v1);
            __nv_bfloat16 l0 = __float2bfloat16(v0 - __bfloat162float(h0));
            __nv_bfloat16 l1 = __float2bfloat16(v1 - __bfloat162float(h1));
            __nv_bfloat162 hp; hp.x = h0; hp.y = h1;
            __nv_bfloat162 lp; lp.x = l0; lp.y = l1;
            *(__nv_bfloat162*)(Oh + base1 + col) = hp;
            *(__nv_bfloat162*)(Ol + base1 + col) = lp;
        }
    }
}

// ---------------- launch -----------------------------------------------------
extern "C" void kernel_launch(void* const* d_in, const int* in_sizes, int n_in,
                              void* d_out, int out_size)
{
    const float* x  = (const float*)d_in[0];
    float* out = (float*)d_out;

    void *pqh, *pql, *pkh, *pkl, *pvh, *pvl, *pxh, *pxl, *pwh, *pwl, *path, *patl, *prope;
    cudaGetSymbolAddress(&pqh, g_qh);  cudaGetSymbolAddress(&pql, g_ql);
    cudaGetSymbolAddress(&pkh, g_kh);  cudaGetSymbolAddress(&pkl, g_kl);
    cudaGetSymbolAddress(&pvh, g_vh);  cudaGetSymbolAddress(&pvl, g_vl);
    cudaGetSymbolAddress(&pxh, g_xh);  cudaGetSymbolAddress(&pxl, g_xl);
    cudaGetSymbolAddress(&pwh, g_wh);  cudaGetSymbolAddress(&pwl, g_wl);
    cudaGetSymbolAddress(&path, g_ath); cudaGetSymbolAddress(&patl, g_atl);
    cudaGetSymbolAddress(&prope, g_rope);

    cudaFuncSetAttribute(gemm_mma<1>, cudaFuncAttributeMaxDynamicSharedMemorySize, GSMEM);
    cudaFuncSetAttribute(gemm_mma<0>, cudaFuncAttributeMaxDynamicSharedMemorySize, GSMEM);
    cudaFuncSetAttribute(flash_mma, cudaFuncAttributeMaxDynamicSharedMemorySize, FSMEM);

    __nv_bfloat16* xh = (__nv_bfloat16*)pxh;
    __nv_bfloat16* xl = (__nv_bfloat16*)pxl;
    __nv_bfloat16* wh = (__nv_bfloat16*)pwh;
    __nv_bfloat16* wl = (__nv_bfloat16*)pwl;

    // RoPE table + fused splits
    rope_kernel<<<(S_ * 32 + 255) / 256, 256>>>((float2*)prope);
    split_all<<<(8 * RW) / 256, 256>>>(x, (const float*)d_in[1], (const float*)d_in[2],
                                       (const float*)d_in[3], (const float*)d_in[4],
                                       xh, xl, wh, wl);

    // fused QKV projection (RoPE/scale in epilogue) -> bf16 hi/lo [B,H,S,hd]
    dim3 qkvgrid(3 * D_ / 128, MTOT / 128);   // (24, 32)
    gemm_mma<1><<<qkvgrid, 256, GSMEM>>>(xh, xl, wh, wl, nullptr,
        (__nv_bfloat16*)pqh, (__nv_bfloat16*)pql,
        (__nv_bfloat16*)pkh, (__nv_bfloat16*)pkl,
        (__nv_bfloat16*)pvh, (__nv_bfloat16*)pvl);

    // tensor-core causal flash attention -> bf16 hi/lo [B,S,D]
    dim3 agrid(S_ / 64, B_ * H_);        // (32, 32) = 1024 CTAs, 2/SM
    flash_mma<<<agrid, 128, FSMEM>>>((const __nv_bfloat16*)pqh, (const __nv_bfloat16*)pql,
                                     (const __nv_bfloat16*)pkh, (const __nv_bfloat16*)pkl,
                                     (const __nv_bfloat16*)pvh, (const __nv_bfloat16*)pvl,
                                     (__nv_bfloat16*)path, (__nv_bfloat16*)patl);

    // output projection -> d_out (fp32)
    dim3 ogrid(D_ / 128, MTOT / 128);    // (8, 32)
    gemm_mma<0><<<ogrid, 256, GSMEM>>>((const __nv_bfloat16*)path, (const __nv_bfloat16*)patl,
                                       wh + 3*(size_t)D_*D_, wl + 3*(size_t)D_*D_,
                                       out, nullptr, nullptr, nullptr, nullptr, nullptr, nullptr);
}